// round 3
// baseline (speedup 1.0000x reference)
#include <cuda_runtime.h>
#include <cstddef>

#define NN 100000
#define NNZ_MAX 3300000

// ---------------- scratch (static device globals; no allocation) ----------------
__device__ int   g_deg[NN];
__device__ int   g_cursor[NN];
__device__ int   g_rowptr[NN + 1];
__device__ int   g_colidx[NNZ_MAX];
__device__ float g_csrval[NNZ_MAX];
__device__ float g_G[(size_t)NN * 128];   // post-GEMM buffer (A's operand)
__device__ float g_H[(size_t)NN * 128];   // post-SpMM/ReLU buffer

// ---------------- CSR build ----------------
__global__ void zero_deg_kernel() {
    int i = blockIdx.x * blockDim.x + threadIdx.x;
    if (i < NN) g_deg[i] = 0;
}

__global__ void histo_kernel(const int* __restrict__ rows, int nnz) {
    int e = blockIdx.x * blockDim.x + threadIdx.x;
    if (e < nnz) atomicAdd(&g_deg[rows[e]], 1);
}

// single-block exclusive scan over N=100K (1024 threads x ~98 elems each)
__global__ void scan_kernel() {
    __shared__ int s[1024];
    const int tid = threadIdx.x;
    const int CH = (NN + 1023) / 1024;   // 98
    const int base = tid * CH;

    int sum = 0;
    for (int i = 0; i < CH; i++) {
        int idx = base + i;
        if (idx < NN) sum += g_deg[idx];
    }
    s[tid] = sum;
    __syncthreads();
    for (int off = 1; off < 1024; off <<= 1) {
        int t = (tid >= off) ? s[tid - off] : 0;
        __syncthreads();
        s[tid] += t;
        __syncthreads();
    }
    int run = s[tid] - sum;   // exclusive prefix of this thread's chunk
    for (int i = 0; i < CH; i++) {
        int idx = base + i;
        if (idx < NN) {
            g_rowptr[idx] = run;
            g_cursor[idx] = run;
            run += g_deg[idx];
        }
    }
    if (tid == 1023) g_rowptr[NN] = s[1023];
}

__global__ void scatter_kernel(const int* __restrict__ rows, const int* __restrict__ cols,
                               const float* __restrict__ vals, int nnz) {
    int e = blockIdx.x * blockDim.x + threadIdx.x;
    if (e < nnz) {
        int r = rows[e];
        int pos = atomicAdd(&g_cursor[r], 1);
        g_colidx[pos] = cols[e];
        g_csrval[pos] = vals[e];
    }
}

// ---------------- dense GEMM: C[N,DOUT] = H[N,128] @ W[128,DOUT] ----------------
// 64-row block tile, BK=64 k-chunks (static smem exactly <=48KB at DOUT=128).
template <int DOUT>
__global__ __launch_bounds__(256) void gemm_kernel(const float* __restrict__ H,
                                                   const float* __restrict__ W,
                                                   float* __restrict__ C) {
    constexpr int BM = 64;
    constexpr int BK = 64;
    constexpr int CT = DOUT / 4;     // col-threads (each covers 4 cols)
    constexpr int RT = 256 / CT;     // row-threads
    constexpr int TM = BM / RT;      // rows per thread

    __shared__ float Hsh[BM][BK];
    __shared__ float Wsh[BK][DOUT];

    const int t    = threadIdx.x;
    const int colt = t % CT;
    const int rowt = t / CT;
    const int row0 = blockIdx.x * BM;

    float acc[TM][4];
#pragma unroll
    for (int i = 0; i < TM; i++) {
        acc[i][0] = 0.f; acc[i][1] = 0.f; acc[i][2] = 0.f; acc[i][3] = 0.f;
    }

    for (int kc = 0; kc < 128; kc += BK) {
        // load H tile (guard rows past N with zeros)
        {
            constexpr int NV = BM * BK / 4;      // float4 slots
            constexpr int F4PR = BK / 4;
            for (int s = t; s < NV; s += 256) {
                int r = s / F4PR, c4 = s % F4PR;
                float4 v = make_float4(0.f, 0.f, 0.f, 0.f);
                int grow = row0 + r;
                if (grow < NN)
                    v = *(const float4*)(H + (size_t)grow * 128 + kc + c4 * 4);
                *(float4*)&Hsh[r][c4 * 4] = v;
            }
        }
        // load W tile
        {
            constexpr int NV = BK * DOUT / 4;
            constexpr int F4PR = DOUT / 4;
            for (int s = t; s < NV; s += 256) {
                int k = s / F4PR, c4 = s % F4PR;
                *(float4*)&Wsh[k][c4 * 4] =
                    *(const float4*)(W + (size_t)(kc + k) * DOUT + c4 * 4);
            }
        }
        __syncthreads();

#pragma unroll 8
        for (int k = 0; k < BK; k++) {
            float4 w = *(float4*)&Wsh[k][colt * 4];
#pragma unroll
            for (int i = 0; i < TM; i++) {
                float h = Hsh[rowt * TM + i][k];
                acc[i][0] += h * w.x;
                acc[i][1] += h * w.y;
                acc[i][2] += h * w.z;
                acc[i][3] += h * w.w;
            }
        }
        __syncthreads();
    }

#pragma unroll
    for (int i = 0; i < TM; i++) {
        int grow = row0 + rowt * TM + i;
        if (grow < NN) {
            float4 v = make_float4(acc[i][0], acc[i][1], acc[i][2], acc[i][3]);
            *(float4*)(C + (size_t)grow * DOUT + colt * 4) = v;
        }
    }
}

// ---------------- SpMM (CSR gather): out[r] = act(sum val*G[col] + bias) ----------------
// one warp per row; d=128: float4 per lane; 4-edge unroll for MLP.
template <bool RELU>
__global__ __launch_bounds__(256) void spmm128_kernel(const float* __restrict__ G,
                                                      const float* __restrict__ bias,
                                                      float* __restrict__ out) {
    int r = (blockIdx.x * blockDim.x + threadIdx.x) >> 5;
    if (r >= NN) return;
    int lane = threadIdx.x & 31;
    int beg = g_rowptr[r], end = g_rowptr[r + 1];

    float4 acc = make_float4(0.f, 0.f, 0.f, 0.f);
    int e = beg;
#pragma unroll 1
    for (; e + 4 <= end; e += 4) {
        int c0 = g_colidx[e];     int c1 = g_colidx[e + 1];
        int c2 = g_colidx[e + 2]; int c3 = g_colidx[e + 3];
        float v0 = g_csrval[e];     float v1 = g_csrval[e + 1];
        float v2 = g_csrval[e + 2]; float v3 = g_csrval[e + 3];
        float4 a = *((const float4*)(G + (size_t)c0 * 128) + lane);
        float4 b = *((const float4*)(G + (size_t)c1 * 128) + lane);
        float4 c = *((const float4*)(G + (size_t)c2 * 128) + lane);
        float4 d = *((const float4*)(G + (size_t)c3 * 128) + lane);
        acc.x += v0 * a.x + v1 * b.x + v2 * c.x + v3 * d.x;
        acc.y += v0 * a.y + v1 * b.y + v2 * c.y + v3 * d.y;
        acc.z += v0 * a.z + v1 * b.z + v2 * c.z + v3 * d.z;
        acc.w += v0 * a.w + v1 * b.w + v2 * c.w + v3 * d.w;
    }
#pragma unroll 1
    for (; e < end; e++) {
        int c0 = g_colidx[e];
        float v0 = g_csrval[e];
        float4 a = *((const float4*)(G + (size_t)c0 * 128) + lane);
        acc.x += v0 * a.x; acc.y += v0 * a.y;
        acc.z += v0 * a.z; acc.w += v0 * a.w;
    }
    float4 b4 = *((const float4*)bias + lane);
    acc.x += b4.x; acc.y += b4.y; acc.z += b4.z; acc.w += b4.w;
    if (RELU) {
        acc.x = fmaxf(acc.x, 0.f); acc.y = fmaxf(acc.y, 0.f);
        acc.z = fmaxf(acc.z, 0.f); acc.w = fmaxf(acc.w, 0.f);
    }
    *((float4*)(out + (size_t)r * 128) + lane) = acc;
}

// d=64 final layer: float2 per lane, no ReLU
__global__ __launch_bounds__(256) void spmm64_kernel(const float* __restrict__ G,
                                                     const float* __restrict__ bias,
                                                     float* __restrict__ out) {
    int r = (blockIdx.x * blockDim.x + threadIdx.x) >> 5;
    if (r >= NN) return;
    int lane = threadIdx.x & 31;
    int beg = g_rowptr[r], end = g_rowptr[r + 1];

    float2 acc = make_float2(0.f, 0.f);
    int e = beg;
#pragma unroll 1
    for (; e + 4 <= end; e += 4) {
        int c0 = g_colidx[e];     int c1 = g_colidx[e + 1];
        int c2 = g_colidx[e + 2]; int c3 = g_colidx[e + 3];
        float v0 = g_csrval[e];     float v1 = g_csrval[e + 1];
        float v2 = g_csrval[e + 2]; float v3 = g_csrval[e + 3];
        float2 a = *((const float2*)(G + (size_t)c0 * 64) + lane);
        float2 b = *((const float2*)(G + (size_t)c1 * 64) + lane);
        float2 c = *((const float2*)(G + (size_t)c2 * 64) + lane);
        float2 d = *((const float2*)(G + (size_t)c3 * 64) + lane);
        acc.x += v0 * a.x + v1 * b.x + v2 * c.x + v3 * d.x;
        acc.y += v0 * a.y + v1 * b.y + v2 * c.y + v3 * d.y;
    }
#pragma unroll 1
    for (; e < end; e++) {
        int c0 = g_colidx[e];
        float v0 = g_csrval[e];
        float2 a = *((const float2*)(G + (size_t)c0 * 64) + lane);
        acc.x += v0 * a.x; acc.y += v0 * a.y;
    }
    float2 b2 = *((const float2*)bias + lane);
    acc.x += b2.x; acc.y += b2.y;
    *((float2*)(out + (size_t)r * 64) + lane) = acc;
}

// ---------------- launch ----------------
extern "C" void kernel_launch(void* const* d_in, const int* in_sizes, int n_in,
                              void* d_out, int out_size) {
    (void)n_in; (void)out_size;
    const float* X    = (const float*)d_in[0];
    const int*   rows = (const int*)  d_in[1];
    const int*   cols = (const int*)  d_in[2];
    const float* vals = (const float*)d_in[3];
    const float* W1   = (const float*)d_in[4];
    const float* b1   = (const float*)d_in[5];
    const float* W2   = (const float*)d_in[6];
    const float* b2   = (const float*)d_in[7];
    const float* W3   = (const float*)d_in[8];
    const float* b3   = (const float*)d_in[9];
    float* out = (float*)d_out;
    const int nnz = in_sizes[1];

    float *G = nullptr, *H = nullptr;
    cudaGetSymbolAddress((void**)&G, g_G);
    cudaGetSymbolAddress((void**)&H, g_H);

    const int TB = 256;
    const int gemm_blocks = (NN + 63) / 64;          // 1563
    const int spmm_blocks = (NN + 7) / 8;            // 12500 (8 warps/block)

    // CSR build (per launch, deterministic work)
    zero_deg_kernel<<<(NN + TB - 1) / TB, TB>>>();
    histo_kernel<<<(nnz + TB - 1) / TB, TB>>>(rows, nnz);
    scan_kernel<<<1, 1024>>>();
    scatter_kernel<<<(nnz + TB - 1) / TB, TB>>>(rows, cols, vals, nnz);

    // layer 1: G = X@W1 ; H = relu(A G + b1)
    gemm_kernel<128><<<gemm_blocks, TB>>>(X, W1, G);
    spmm128_kernel<true><<<spmm_blocks, TB>>>(G, b1, H);

    // layer 2: G = H@W2 ; H = relu(A G + b2)
    gemm_kernel<128><<<gemm_blocks, TB>>>(H, W2, G);
    spmm128_kernel<true><<<spmm_blocks, TB>>>(G, b2, H);

    // layer 3: G = H@W3 (64-wide) ; out = A G + b3
    gemm_kernel<64><<<gemm_blocks, TB>>>(H, W3, G);
    spmm64_kernel<<<spmm_blocks, TB>>>(G, b3, out);
}

// round 4
// speedup vs baseline: 1.4496x; 1.4496x over previous
#include <cuda_runtime.h>
#include <cuda_fp16.h>
#include <cstddef>

#define NN 100000
#define NNZ_MAX 3300000
#define NB_SCAN 391              // ceil(NN/256)

// ---------------- scratch (static device globals; no allocation) ----------------
__device__ int    g_deg[NN];
__device__ int    g_cursor[NN];
__device__ int    g_rowptr[NN + 1];
__device__ int    g_bsum[512];
__device__ int2   g_edge[NNZ_MAX];               // {col, val as int-bits}
__device__ __half g_G[(size_t)NN * 128];         // post-GEMM buffer (SpMM gather operand), fp16
__device__ float  g_H[(size_t)NN * 128];         // post-SpMM/ReLU buffer, fp32

// ---------------- CSR build ----------------
__global__ void zero_deg_kernel() {
    int i = blockIdx.x * blockDim.x + threadIdx.x;
    if (i < NN) g_deg[i] = 0;
}

__global__ void histo_kernel(const int* __restrict__ rows, int nnz) {
    int e = blockIdx.x * blockDim.x + threadIdx.x;
    if (e < nnz) atomicAdd(&g_deg[rows[e]], 1);
}

// scan stage 1: per-block (256-wide) sums of deg
__global__ void scan1_kernel() {
    __shared__ int s[256];
    int t = threadIdx.x;
    int i = blockIdx.x * 256 + t;
    s[t] = (i < NN) ? g_deg[i] : 0;
    __syncthreads();
    for (int off = 128; off > 0; off >>= 1) {
        if (t < off) s[t] += s[t + off];
        __syncthreads();
    }
    if (t == 0) g_bsum[blockIdx.x] = s[0];
}

// scan stage 2: single block exclusive scan over NB_SCAN block sums
__global__ void scan2_kernel() {
    __shared__ int s[512];
    int t = threadIdx.x;
    int v = (t < NB_SCAN) ? g_bsum[t] : 0;
    s[t] = v;
    __syncthreads();
    for (int off = 1; off < 512; off <<= 1) {
        int x = (t >= off) ? s[t - off] : 0;
        __syncthreads();
        s[t] += x;
        __syncthreads();
    }
    if (t < NB_SCAN) g_bsum[t] = s[t] - v;   // exclusive
}

// scan stage 3: per-block local scan + global offset -> rowptr, cursor
__global__ void scan3_kernel() {
    __shared__ int s[256];
    int t = threadIdx.x;
    int i = blockIdx.x * 256 + t;
    int d = (i < NN) ? g_deg[i] : 0;
    s[t] = d;
    __syncthreads();
    for (int off = 1; off < 256; off <<= 1) {
        int x = (t >= off) ? s[t - off] : 0;
        __syncthreads();
        s[t] += x;
        __syncthreads();
    }
    int base = g_bsum[blockIdx.x];
    if (i < NN) {
        int excl = base + s[t] - d;
        g_rowptr[i] = excl;
        g_cursor[i] = excl;
        if (i == NN - 1) g_rowptr[NN] = base + s[t];
    }
}

__global__ void scatter_kernel(const int* __restrict__ rows, const int* __restrict__ cols,
                               const float* __restrict__ vals, int nnz) {
    int e = blockIdx.x * blockDim.x + threadIdx.x;
    if (e < nnz) {
        int r = rows[e];
        int pos = atomicAdd(&g_cursor[r], 1);
        g_edge[pos] = make_int2(cols[e], __float_as_int(vals[e]));
    }
}

// ---------------- dense GEMM: G[N,DOUT](fp16) = H[N,128](fp32) @ W[128,DOUT] ----------------
// 8x8 register tile, transposed-H smem so both operands use LDS.128.
template <int BM, int DOUT>
__global__ __launch_bounds__(256) void gemm_kernel(const float* __restrict__ H,
                                                   const float* __restrict__ W,
                                                   __half* __restrict__ G) {
    constexpr int BK = 32;
    constexpr int TM = 8, TN = 8;
    constexpr int CT = DOUT / TN;        // 16 (d=128) or 8 (d=64)
    constexpr int RT = 256 / CT;         // 16 or 32
    static_assert(RT * TM == BM, "tile mismatch");

    __shared__ float Hs[BK][BM + 4];     // transposed: Hs[k][m]
    __shared__ float Ws[BK][DOUT];

    const int t    = threadIdx.x;
    const int colt = t % CT;
    const int rowt = t / CT;
    const int row0 = blockIdx.x * BM;

    float acc[TM][TN];
#pragma unroll
    for (int i = 0; i < TM; i++)
#pragma unroll
        for (int j = 0; j < TN; j++) acc[i][j] = 0.f;

    for (int kc = 0; kc < 128; kc += BK) {
        // load H tile (transpose into smem)
        {
            constexpr int F4PR = BK / 4;             // 8 float4 per row
            constexpr int NV = BM * BK / 4;
#pragma unroll
            for (int s = t; s < NV; s += 256) {
                int r = s / F4PR, c4 = s % F4PR;
                float4 v = make_float4(0.f, 0.f, 0.f, 0.f);
                int gr = row0 + r;
                if (gr < NN)
                    v = *(const float4*)(H + (size_t)gr * 128 + kc + c4 * 4);
                Hs[c4 * 4 + 0][r] = v.x;
                Hs[c4 * 4 + 1][r] = v.y;
                Hs[c4 * 4 + 2][r] = v.z;
                Hs[c4 * 4 + 3][r] = v.w;
            }
        }
        // load W tile
        {
            constexpr int WF4 = DOUT / 4;
            constexpr int NV = BK * DOUT / 4;
#pragma unroll
            for (int s = t; s < NV; s += 256) {
                int k = s / WF4, c4 = s % WF4;
                *(float4*)&Ws[k][c4 * 4] =
                    *(const float4*)(W + (size_t)(kc + k) * DOUT + c4 * 4);
            }
        }
        __syncthreads();

#pragma unroll
        for (int k = 0; k < BK; k++) {
            float4 h0 = *(float4*)&Hs[k][rowt * TM];
            float4 h1 = *(float4*)&Hs[k][rowt * TM + 4];
            float4 w0 = *(float4*)&Ws[k][colt * TN];
            float4 w1 = *(float4*)&Ws[k][colt * TN + 4];
            float hr[8] = {h0.x, h0.y, h0.z, h0.w, h1.x, h1.y, h1.z, h1.w};
            float wr[8] = {w0.x, w0.y, w0.z, w0.w, w1.x, w1.y, w1.z, w1.w};
#pragma unroll
            for (int i = 0; i < TM; i++)
#pragma unroll
                for (int j = 0; j < TN; j++)
                    acc[i][j] += hr[i] * wr[j];
        }
        __syncthreads();
    }

    // epilogue: convert to fp16 and store 8 halves (16B) per row
#pragma unroll
    for (int i = 0; i < TM; i++) {
        int gr = row0 + rowt * TM + i;
        if (gr < NN) {
            __half2 p0 = __floats2half2_rn(acc[i][0], acc[i][1]);
            __half2 p1 = __floats2half2_rn(acc[i][2], acc[i][3]);
            __half2 p2 = __floats2half2_rn(acc[i][4], acc[i][5]);
            __half2 p3 = __floats2half2_rn(acc[i][6], acc[i][7]);
            uint4 o;
            o.x = *(unsigned*)&p0; o.y = *(unsigned*)&p1;
            o.z = *(unsigned*)&p2; o.w = *(unsigned*)&p3;
            *(uint4*)(G + (size_t)gr * DOUT + colt * TN) = o;
        }
    }
}

// ---------------- SpMM (CSR gather, fp16 operand): out[r] = act(sum val*G[col] + bias) ----------------
template <bool RELU>
__global__ __launch_bounds__(256) void spmm128_kernel(const __half* __restrict__ G,
                                                      const float* __restrict__ bias,
                                                      float* __restrict__ out) {
    int r = (blockIdx.x * blockDim.x + threadIdx.x) >> 5;
    if (r >= NN) return;
    int lane = threadIdx.x & 31;
    int beg = g_rowptr[r], end = g_rowptr[r + 1];

    float4 acc = make_float4(0.f, 0.f, 0.f, 0.f);
    int e = beg;
#pragma unroll 1
    for (; e + 4 <= end; e += 4) {
        int2 e0 = g_edge[e];     int2 e1 = g_edge[e + 1];
        int2 e2 = g_edge[e + 2]; int2 e3 = g_edge[e + 3];
        uint2 qa = *((const uint2*)(G + (size_t)e0.x * 128) + lane);
        uint2 qb = *((const uint2*)(G + (size_t)e1.x * 128) + lane);
        uint2 qc = *((const uint2*)(G + (size_t)e2.x * 128) + lane);
        uint2 qd = *((const uint2*)(G + (size_t)e3.x * 128) + lane);
        float v0 = __int_as_float(e0.y), v1 = __int_as_float(e1.y);
        float v2 = __int_as_float(e2.y), v3 = __int_as_float(e3.y);
        float2 a0 = __half22float2(*(__half2*)&qa.x), a1 = __half22float2(*(__half2*)&qa.y);
        float2 b0 = __half22float2(*(__half2*)&qb.x), b1 = __half22float2(*(__half2*)&qb.y);
        float2 c0 = __half22float2(*(__half2*)&qc.x), c1 = __half22float2(*(__half2*)&qc.y);
        float2 d0 = __half22float2(*(__half2*)&qd.x), d1 = __half22float2(*(__half2*)&qd.y);
        acc.x += v0 * a0.x + v1 * b0.x + v2 * c0.x + v3 * d0.x;
        acc.y += v0 * a0.y + v1 * b0.y + v2 * c0.y + v3 * d0.y;
        acc.z += v0 * a1.x + v1 * b1.x + v2 * c1.x + v3 * d1.x;
        acc.w += v0 * a1.y + v1 * b1.y + v2 * c1.y + v3 * d1.y;
    }
#pragma unroll 1
    for (; e < end; e++) {
        int2 e0 = g_edge[e];
        float v0 = __int_as_float(e0.y);
        uint2 qa = *((const uint2*)(G + (size_t)e0.x * 128) + lane);
        float2 a0 = __half22float2(*(__half2*)&qa.x), a1 = __half22float2(*(__half2*)&qa.y);
        acc.x += v0 * a0.x; acc.y += v0 * a0.y;
        acc.z += v0 * a1.x; acc.w += v0 * a1.y;
    }
    float4 b4 = *((const float4*)bias + lane);
    acc.x += b4.x; acc.y += b4.y; acc.z += b4.z; acc.w += b4.w;
    if (RELU) {
        acc.x = fmaxf(acc.x, 0.f); acc.y = fmaxf(acc.y, 0.f);
        acc.z = fmaxf(acc.z, 0.f); acc.w = fmaxf(acc.w, 0.f);
    }
    *((float4*)(out + (size_t)r * 128) + lane) = acc;
}

// d=64 final layer: 2 halves per lane, no ReLU, fp32 out
__global__ __launch_bounds__(256) void spmm64_kernel(const __half* __restrict__ G,
                                                     const float* __restrict__ bias,
                                                     float* __restrict__ out) {
    int r = (blockIdx.x * blockDim.x + threadIdx.x) >> 5;
    if (r >= NN) return;
    int lane = threadIdx.x & 31;
    int beg = g_rowptr[r], end = g_rowptr[r + 1];

    float2 acc = make_float2(0.f, 0.f);
    int e = beg;
#pragma unroll 1
    for (; e + 4 <= end; e += 4) {
        int2 e0 = g_edge[e];     int2 e1 = g_edge[e + 1];
        int2 e2 = g_edge[e + 2]; int2 e3 = g_edge[e + 3];
        unsigned qa = *((const unsigned*)(G + (size_t)e0.x * 64) + lane);
        unsigned qb = *((const unsigned*)(G + (size_t)e1.x * 64) + lane);
        unsigned qc = *((const unsigned*)(G + (size_t)e2.x * 64) + lane);
        unsigned qd = *((const unsigned*)(G + (size_t)e3.x * 64) + lane);
        float v0 = __int_as_float(e0.y), v1 = __int_as_float(e1.y);
        float v2 = __int_as_float(e2.y), v3 = __int_as_float(e3.y);
        float2 a = __half22float2(*(__half2*)&qa);
        float2 b = __half22float2(*(__half2*)&qb);
        float2 c = __half22float2(*(__half2*)&qc);
        float2 d = __half22float2(*(__half2*)&qd);
        acc.x += v0 * a.x + v1 * b.x + v2 * c.x + v3 * d.x;
        acc.y += v0 * a.y + v1 * b.y + v2 * c.y + v3 * d.y;
    }
#pragma unroll 1
    for (; e < end; e++) {
        int2 e0 = g_edge[e];
        float v0 = __int_as_float(e0.y);
        unsigned qa = *((const unsigned*)(G + (size_t)e0.x * 64) + lane);
        float2 a = __half22float2(*(__half2*)&qa);
        acc.x += v0 * a.x; acc.y += v0 * a.y;
    }
    float2 b2 = *((const float2*)bias + lane);
    acc.x += b2.x; acc.y += b2.y;
    *((float2*)(out + (size_t)r * 64) + lane) = acc;
}

// ---------------- launch ----------------
extern "C" void kernel_launch(void* const* d_in, const int* in_sizes, int n_in,
                              void* d_out, int out_size) {
    (void)n_in; (void)out_size;
    const float* X    = (const float*)d_in[0];
    const int*   rows = (const int*)  d_in[1];
    const int*   cols = (const int*)  d_in[2];
    const float* vals = (const float*)d_in[3];
    const float* W1   = (const float*)d_in[4];
    const float* b1   = (const float*)d_in[5];
    const float* W2   = (const float*)d_in[6];
    const float* b2   = (const float*)d_in[7];
    const float* W3   = (const float*)d_in[8];
    const float* b3   = (const float*)d_in[9];
    float* out = (float*)d_out;
    const int nnz = in_sizes[1];

    __half* G = nullptr;
    float*  H = nullptr;
    cudaGetSymbolAddress((void**)&G, g_G);
    cudaGetSymbolAddress((void**)&H, g_H);

    const int TB = 256;
    const int spmm_blocks = (NN + 7) / 8;            // 8 warps/block

    // CSR build
    zero_deg_kernel<<<(NN + TB - 1) / TB, TB>>>();
    histo_kernel<<<(nnz + TB - 1) / TB, TB>>>(rows, nnz);
    scan1_kernel<<<NB_SCAN, 256>>>();
    scan2_kernel<<<1, 512>>>();
    scan3_kernel<<<NB_SCAN, 256>>>();
    scatter_kernel<<<(nnz + TB - 1) / TB, TB>>>(rows, cols, vals, nnz);

    // layer 1: G = fp16(X@W1) ; H = relu(A G + b1)
    gemm_kernel<128, 128><<<(NN + 127) / 128, TB>>>(X, W1, G);
    spmm128_kernel<true><<<spmm_blocks, TB>>>(G, b1, H);

    // layer 2: G = fp16(H@W2) ; H = relu(A G + b2)
    gemm_kernel<128, 128><<<(NN + 127) / 128, TB>>>(H, W2, G);
    spmm128_kernel<true><<<spmm_blocks, TB>>>(G, b2, H);

    // layer 3: G = fp16(H@W3) (64-wide) ; out = A G + b3
    gemm_kernel<256, 64><<<(NN + 255) / 256, TB>>>(H, W3, G);
    spmm64_kernel<<<spmm_blocks, TB>>>(G, b3, out);
}

// round 7
// speedup vs baseline: 2.0825x; 1.4367x over previous
#include <cuda_runtime.h>
#include <cuda_fp16.h>
#include <cstddef>
#include <cstdint>

#define NN 100000
#define NNZ_MAX 3300000
#define NB_SCAN 391              // ceil(NN/256)

// ---------------- scratch (static device globals; no allocation) ----------------
__device__ int    g_deg[NN];
__device__ int    g_cursor[NN];
__device__ int    g_rowptr[NN + 1];
__device__ int    g_bsum[512];
__device__ int2   g_edge[NNZ_MAX];               // {col, val as int-bits}
__device__ __half g_A[(size_t)NN * 128];         // fp16 GEMM input (Xh, then H after each SpMM)
__device__ __half g_G[(size_t)NN * 128];         // fp16 GEMM output (SpMM gather operand)
__device__ __half g_W1h[128 * 128];
__device__ __half g_W2h[128 * 128];
__device__ __half g_W3h[128 * 64];

// ---------------- CSR build ----------------
__global__ void zero_deg_kernel() {
    int i = blockIdx.x * blockDim.x + threadIdx.x;
    if (i < NN) g_deg[i] = 0;
}

__global__ void histo_kernel(const int* __restrict__ rows, int nnz) {
    int e = blockIdx.x * blockDim.x + threadIdx.x;
    if (e < nnz) atomicAdd(&g_deg[rows[e]], 1);
}

__global__ void scan1_kernel() {
    __shared__ int s[256];
    int t = threadIdx.x;
    int i = blockIdx.x * 256 + t;
    s[t] = (i < NN) ? g_deg[i] : 0;
    __syncthreads();
    for (int off = 128; off > 0; off >>= 1) {
        if (t < off) s[t] += s[t + off];
        __syncthreads();
    }
    if (t == 0) g_bsum[blockIdx.x] = s[0];
}

__global__ void scan2_kernel() {
    __shared__ int s[512];
    int t = threadIdx.x;
    int v = (t < NB_SCAN) ? g_bsum[t] : 0;
    s[t] = v;
    __syncthreads();
    for (int off = 1; off < 512; off <<= 1) {
        int x = (t >= off) ? s[t - off] : 0;
        __syncthreads();
        s[t] += x;
        __syncthreads();
    }
    if (t < NB_SCAN) g_bsum[t] = s[t] - v;   // exclusive
}

__global__ void scan3_kernel() {
    __shared__ int s[256];
    int t = threadIdx.x;
    int i = blockIdx.x * 256 + t;
    int d = (i < NN) ? g_deg[i] : 0;
    s[t] = d;
    __syncthreads();
    for (int off = 1; off < 256; off <<= 1) {
        int x = (t >= off) ? s[t - off] : 0;
        __syncthreads();
        s[t] += x;
        __syncthreads();
    }
    int base = g_bsum[blockIdx.x];
    if (i < NN) {
        int excl = base + s[t] - d;
        g_rowptr[i] = excl;
        g_cursor[i] = excl;
        if (i == NN - 1) g_rowptr[NN] = base + s[t];
    }
}

__global__ void scatter_kernel(const int* __restrict__ rows, const int* __restrict__ cols,
                               const float* __restrict__ vals, int nnz) {
    int e = blockIdx.x * blockDim.x + threadIdx.x;
    if (e < nnz) {
        int r = rows[e];
        int pos = atomicAdd(&g_cursor[r], 1);
        g_edge[pos] = make_int2(cols[e], __float_as_int(vals[e]));
    }
}

// ---------------- fp32 -> fp16 converts ----------------
__global__ void cvt_f2h_kernel(const float* __restrict__ src, __half* __restrict__ dst, int n4) {
    int i = blockIdx.x * blockDim.x + threadIdx.x;
    if (i < n4) {
        float4 v = *((const float4*)src + i);
        __half2 p0 = __floats2half2_rn(v.x, v.y);
        __half2 p1 = __floats2half2_rn(v.z, v.w);
        uint2 o; o.x = *(unsigned*)&p0; o.y = *(unsigned*)&p1;
        *((uint2*)dst + i) = o;
    }
}

// ---------------- tensor-core GEMM: G[N,DOUT](fp16) = A[N,128](fp16) @ W[128,DOUT](fp16) ----------------
__device__ __forceinline__ void mma16816(float* d, const unsigned* a, const unsigned* b) {
    asm volatile(
        "mma.sync.aligned.m16n8k16.row.col.f32.f16.f16.f32 "
        "{%0,%1,%2,%3}, {%4,%5,%6,%7}, {%8,%9}, {%0,%1,%2,%3};\n"
        : "+f"(d[0]), "+f"(d[1]), "+f"(d[2]), "+f"(d[3])
        : "r"(a[0]), "r"(a[1]), "r"(a[2]), "r"(a[3]),
          "r"(b[0]), "r"(b[1]));
}
__device__ __forceinline__ void ldsm_x4(unsigned* r, uint32_t addr) {
    asm volatile("ldmatrix.sync.aligned.m8n8.x4.shared.b16 {%0,%1,%2,%3}, [%4];\n"
        : "=r"(r[0]), "=r"(r[1]), "=r"(r[2]), "=r"(r[3]) : "r"(addr));
}
__device__ __forceinline__ void ldsm_x2_trans(unsigned* r, uint32_t addr) {
    asm volatile("ldmatrix.sync.aligned.m8n8.x2.trans.shared.b16 {%0,%1}, [%2];\n"
        : "=r"(r[0]), "=r"(r[1]) : "r"(addr));
}

// BM=128 rows/block, K chunked at BK=64 so smem stays static (<48KB).
// Pitches: A 72 halves (144B), W DOUT+8 halves (272B/144B) -> stride ≡ 4 banks, ldmatrix conflict-free.
template <int DOUT>
__global__ __launch_bounds__(256) void gemm_tc_kernel(const __half* __restrict__ A,
                                                      const __half* __restrict__ W,
                                                      __half* __restrict__ G) {
    constexpr int BM = 128;
    constexpr int BK = 64;
    constexpr int APITCH_H = BK + 8;              // 72 halves = 144B
    constexpr int WPITCH_H = DOUT + 8;            // 136 or 72 halves
    // warp tiling: 8 warps
    constexpr int WN = 32;
    constexpr int WM = (DOUT == 128) ? 64 : 32;   // 2x4 or 4x2 warp grid
    constexpr int MT = WM / 16;                   // 4 or 2
    constexpr int NT = WN / 8;                    // 4

    __shared__ __half As[BM * APITCH_H];          // 18432 B
    __shared__ __half Ws[BK * WPITCH_H];          // 17408 B (DOUT=128) / 9216 B

    const int t = threadIdx.x;
    const int lane = t & 31;
    const int wid = t >> 5;
    const int warp_m = (DOUT == 128) ? (wid >> 2) : (wid >> 1);
    const int warp_n = (DOUT == 128) ? (wid & 3) : (wid & 1);
    const int row0 = blockIdx.x * BM;

    float acc[MT][NT][4];
#pragma unroll
    for (int i = 0; i < MT; i++)
#pragma unroll
        for (int j = 0; j < NT; j++) {
            acc[i][j][0] = 0.f; acc[i][j][1] = 0.f;
            acc[i][j][2] = 0.f; acc[i][j][3] = 0.f;
        }

    const uint32_t as_base = (uint32_t)__cvta_generic_to_shared(As);
    const uint32_t ws_base = (uint32_t)__cvta_generic_to_shared(Ws);

    for (int kc = 0; kc < 128; kc += BK) {
        // load A tile: 128 rows x 8 uint4 (zero-pad rows past NN)
        {
            uint4* dst = (uint4*)As;
            constexpr int U4PR = BK / 8;          // 8
#pragma unroll
            for (int s = t; s < BM * U4PR; s += 256) {
                int r = s / U4PR, c4 = s % U4PR;
                uint4 v = make_uint4(0, 0, 0, 0);
                int gr = row0 + r;
                if (gr < NN) v = *((const uint4*)(A + (size_t)gr * 128 + kc) + c4);
                dst[r * (APITCH_H / 8) + c4] = v;
            }
        }
        // load W tile: BK rows x DOUT/8 uint4
        {
            constexpr int WU4 = DOUT / 8;
            uint4* dst = (uint4*)Ws;
#pragma unroll
            for (int s = t; s < BK * WU4; s += 256) {
                int r = s / WU4, c4 = s % WU4;
                dst[r * (WPITCH_H / 8) + c4] = *((const uint4*)(W + (size_t)(kc + r) * DOUT) + c4);
            }
        }
        __syncthreads();

#pragma unroll
        for (int k = 0; k < BK; k += 16) {
            unsigned afrag[MT][4];
            unsigned bfrag[NT][2];
#pragma unroll
            for (int mt = 0; mt < MT; mt++) {
                int row = warp_m * WM + mt * 16 + (lane & 15);
                int col = k + ((lane >> 4) << 3);
                ldsm_x4(afrag[mt], as_base + (row * APITCH_H + col) * 2);
            }
#pragma unroll
            for (int nt = 0; nt < NT; nt++) {
                int krow = k + (lane & 15);
                int col = warp_n * WN + nt * 8;
                ldsm_x2_trans(bfrag[nt], ws_base + (krow * WPITCH_H + col) * 2);
            }
#pragma unroll
            for (int mt = 0; mt < MT; mt++)
#pragma unroll
                for (int nt = 0; nt < NT; nt++)
                    mma16816(acc[mt][nt], afrag[mt], bfrag[nt]);
        }
        __syncthreads();
    }

    // epilogue: fp16 store
    const int gID = lane >> 2;
    const int tc = lane & 3;
#pragma unroll
    for (int mt = 0; mt < MT; mt++) {
#pragma unroll
        for (int nt = 0; nt < NT; nt++) {
            int col = warp_n * WN + nt * 8 + tc * 2;
            int r0 = row0 + warp_m * WM + mt * 16 + gID;
            if (r0 < NN) {
                __half2 p = __floats2half2_rn(acc[mt][nt][0], acc[mt][nt][1]);
                *(unsigned*)(G + (size_t)r0 * DOUT + col) = *(unsigned*)&p;
            }
            int r1 = r0 + 8;
            if (r1 < NN) {
                __half2 p = __floats2half2_rn(acc[mt][nt][2], acc[mt][nt][3]);
                *(unsigned*)(G + (size_t)r1 * DOUT + col) = *(unsigned*)&p;
            }
        }
    }
}

// ---------------- SpMM (CSR gather, fp16 in / fp16 out): H[r] = relu(sum val*G[col] + bias) ----------------
__global__ __launch_bounds__(256) void spmm128h_kernel(const __half* __restrict__ G,
                                                       const float* __restrict__ bias,
                                                       __half* __restrict__ out) {
    int r = (blockIdx.x * blockDim.x + threadIdx.x) >> 5;
    if (r >= NN) return;
    int lane = threadIdx.x & 31;
    int beg = g_rowptr[r], end = g_rowptr[r + 1];

    float4 acc = make_float4(0.f, 0.f, 0.f, 0.f);
    int e = beg;
#pragma unroll 1
    for (; e + 4 <= end; e += 4) {
        int2 e0 = g_edge[e];     int2 e1 = g_edge[e + 1];
        int2 e2 = g_edge[e + 2]; int2 e3 = g_edge[e + 3];
        uint2 qa = *((const uint2*)(G + (size_t)e0.x * 128) + lane);
        uint2 qb = *((const uint2*)(G + (size_t)e1.x * 128) + lane);
        uint2 qc = *((const uint2*)(G + (size_t)e2.x * 128) + lane);
        uint2 qd = *((const uint2*)(G + (size_t)e3.x * 128) + lane);
        float v0 = __int_as_float(e0.y), v1 = __int_as_float(e1.y);
        float v2 = __int_as_float(e2.y), v3 = __int_as_float(e3.y);
        float2 a0 = __half22float2(*(__half2*)&qa.x), a1 = __half22float2(*(__half2*)&qa.y);
        float2 b0 = __half22float2(*(__half2*)&qb.x), b1 = __half22float2(*(__half2*)&qb.y);
        float2 c0 = __half22float2(*(__half2*)&qc.x), c1 = __half22float2(*(__half2*)&qc.y);
        float2 d0 = __half22float2(*(__half2*)&qd.x), d1 = __half22float2(*(__half2*)&qd.y);
        acc.x += v0 * a0.x + v1 * b0.x + v2 * c0.x + v3 * d0.x;
        acc.y += v0 * a0.y + v1 * b0.y + v2 * c0.y + v3 * d0.y;
        acc.z += v0 * a1.x + v1 * b1.x + v2 * c1.x + v3 * d1.x;
        acc.w += v0 * a1.y + v1 * b1.y + v2 * c1.y + v3 * d1.y;
    }
#pragma unroll 1
    for (; e < end; e++) {
        int2 e0 = g_edge[e];
        float v0 = __int_as_float(e0.y);
        uint2 qa = *((const uint2*)(G + (size_t)e0.x * 128) + lane);
        float2 a0 = __half22float2(*(__half2*)&qa.x), a1 = __half22float2(*(__half2*)&qa.y);
        acc.x += v0 * a0.x; acc.y += v0 * a0.y;
        acc.z += v0 * a1.x; acc.w += v0 * a1.y;
    }
    float4 b4 = *((const float4*)bias + lane);
    acc.x = fmaxf(acc.x + b4.x, 0.f); acc.y = fmaxf(acc.y + b4.y, 0.f);
    acc.z = fmaxf(acc.z + b4.z, 0.f); acc.w = fmaxf(acc.w + b4.w, 0.f);
    __half2 p0 = __floats2half2_rn(acc.x, acc.y);
    __half2 p1 = __floats2half2_rn(acc.z, acc.w);
    uint2 o; o.x = *(unsigned*)&p0; o.y = *(unsigned*)&p1;
    *((uint2*)(out + (size_t)r * 128) + lane) = o;
}

// d=64 final layer: fp16 gather, fp32 out, no ReLU
__global__ __launch_bounds__(256) void spmm64_kernel(const __half* __restrict__ G,
                                                     const float* __restrict__ bias,
                                                     float* __restrict__ out) {
    int r = (blockIdx.x * blockDim.x + threadIdx.x) >> 5;
    if (r >= NN) return;
    int lane = threadIdx.x & 31;
    int beg = g_rowptr[r], end = g_rowptr[r + 1];

    float2 acc = make_float2(0.f, 0.f);
    int e = beg;
#pragma unroll 1
    for (; e + 4 <= end; e += 4) {
        int2 e0 = g_edge[e];     int2 e1 = g_edge[e + 1];
        int2 e2 = g_edge[e + 2]; int2 e3 = g_edge[e + 3];
        unsigned qa = *((const unsigned*)(G + (size_t)e0.x * 64) + lane);
        unsigned qb = *((const unsigned*)(G + (size_t)e1.x * 64) + lane);
        unsigned qc = *((const unsigned*)(G + (size_t)e2.x * 64) + lane);
        unsigned qd = *((const unsigned*)(G + (size_t)e3.x * 64) + lane);
        float v0 = __int_as_float(e0.y), v1 = __int_as_float(e1.y);
        float v2 = __int_as_float(e2.y), v3 = __int_as_float(e3.y);
        float2 a = __half22float2(*(__half2*)&qa);
        float2 b = __half22float2(*(__half2*)&qb);
        float2 c = __half22float2(*(__half2*)&qc);
        float2 d = __half22float2(*(__half2*)&qd);
        acc.x += v0 * a.x + v1 * b.x + v2 * c.x + v3 * d.x;
        acc.y += v0 * a.y + v1 * b.y + v2 * c.y + v3 * d.y;
    }
#pragma unroll 1
    for (; e < end; e++) {
        int2 e0 = g_edge[e];
        float v0 = __int_as_float(e0.y);
        unsigned qa = *((const unsigned*)(G + (size_t)e0.x * 64) + lane);
        float2 a = __half22float2(*(__half2*)&qa);
        acc.x += v0 * a.x; acc.y += v0 * a.y;
    }
    float2 b2 = *((const float2*)bias + lane);
    acc.x += b2.x; acc.y += b2.y;
    *((float2*)(out + (size_t)r * 64) + lane) = acc;
}

// ---------------- launch ----------------
extern "C" void kernel_launch(void* const* d_in, const int* in_sizes, int n_in,
                              void* d_out, int out_size) {
    (void)n_in; (void)out_size;
    const float* X    = (const float*)d_in[0];
    const int*   rows = (const int*)  d_in[1];
    const int*   cols = (const int*)  d_in[2];
    const float* vals = (const float*)d_in[3];
    const float* W1   = (const float*)d_in[4];
    const float* b1   = (const float*)d_in[5];
    const float* W2   = (const float*)d_in[6];
    const float* b2   = (const float*)d_in[7];
    const float* W3   = (const float*)d_in[8];
    const float* b3   = (const float*)d_in[9];
    float* out = (float*)d_out;
    const int nnz = in_sizes[1];

    __half *A = nullptr, *G = nullptr, *W1h = nullptr, *W2h = nullptr, *W3h = nullptr;
    cudaGetSymbolAddress((void**)&A, g_A);
    cudaGetSymbolAddress((void**)&G, g_G);
    cudaGetSymbolAddress((void**)&W1h, g_W1h);
    cudaGetSymbolAddress((void**)&W2h, g_W2h);
    cudaGetSymbolAddress((void**)&W3h, g_W3h);

    const int TB = 256;
    const int spmm_blocks = (NN + 7) / 8;
    const int gemm_blocks = (NN + 127) / 128;

    // CSR build
    zero_deg_kernel<<<(NN + TB - 1) / TB, TB>>>();
    histo_kernel<<<(nnz + TB - 1) / TB, TB>>>(rows, nnz);
    scan1_kernel<<<NB_SCAN, 256>>>();
    scan2_kernel<<<1, 512>>>();
    scan3_kernel<<<NB_SCAN, 256>>>();
    scatter_kernel<<<(nnz + TB - 1) / TB, TB>>>(rows, cols, vals, nnz);

    // fp16 converts
    cvt_f2h_kernel<<<(NN * 128 / 4 + TB - 1) / TB, TB>>>(X, A, NN * 128 / 4);
    cvt_f2h_kernel<<<(128 * 128 / 4 + TB - 1) / TB, TB>>>(W1, W1h, 128 * 128 / 4);
    cvt_f2h_kernel<<<(128 * 128 / 4 + TB - 1) / TB, TB>>>(W2, W2h, 128 * 128 / 4);
    cvt_f2h_kernel<<<(128 * 64 / 4 + TB - 1) / TB, TB>>>(W3, W3h, 128 * 64 / 4);

    // layer 1: G = Xh@W1h ; A = relu(A_norm G + b1)  (fp16)
    gemm_tc_kernel<128><<<gemm_blocks, TB>>>(A, W1h, G);
    spmm128h_kernel<<<spmm_blocks, TB>>>(G, b1, A);

    // layer 2
    gemm_tc_kernel<128><<<gemm_blocks, TB>>>(A, W2h, G);
    spmm128h_kernel<<<spmm_blocks, TB>>>(G, b2, A);

    // layer 3 (64-wide), fp32 output
    gemm_tc_kernel<64><<<gemm_blocks, TB>>>(A, W3h, G);
    spmm64_kernel<<<spmm_blocks, TB>>>(G, b3, out);
}

// round 8
// speedup vs baseline: 2.1060x; 1.0113x over previous
#include <cuda_runtime.h>
#include <cuda_fp16.h>
#include <cstddef>
#include <cstdint>

#define NN 100000
#define NNZ_MAX 3300000
#define NB_SCAN 391              // ceil(NN/256)

// ---------------- scratch (static device globals; no allocation) ----------------
__device__ int    g_deg[NN];
__device__ int    g_cursor[NN];
__device__ int    g_rowptr[NN + 1];
__device__ int    g_bsum[512];
__device__ int2   g_edge[NNZ_MAX];               // {col, val as int-bits}
__device__ __half g_A[(size_t)NN * 128];         // fp16 H buffer (SpMM output / GEMM input, layers 2-3)
__device__ __half g_G[(size_t)NN * 128];         // fp16 GEMM output (SpMM gather operand)
__device__ __half g_W1h[128 * 128];
__device__ __half g_W2h[128 * 128];
__device__ __half g_W3h[128 * 64];

// ---------------- CSR build ----------------
__global__ void zero_deg_kernel() {
    int i = blockIdx.x * blockDim.x + threadIdx.x;
    if (i < NN) g_deg[i] = 0;
}

// 4 edges per thread for MLP=4 over the ~300cyc atomic latency
__global__ void histo_kernel(const int* __restrict__ rows, int nnz) {
    int base = (blockIdx.x * blockDim.x + threadIdx.x) * 4;
    if (base + 4 <= nnz) {
        int r0 = rows[base], r1 = rows[base + 1], r2 = rows[base + 2], r3 = rows[base + 3];
        atomicAdd(&g_deg[r0], 1);
        atomicAdd(&g_deg[r1], 1);
        atomicAdd(&g_deg[r2], 1);
        atomicAdd(&g_deg[r3], 1);
    } else {
        for (int e = base; e < nnz; e++) atomicAdd(&g_deg[rows[e]], 1);
    }
}

__global__ void scan1_kernel() {
    __shared__ int s[256];
    int t = threadIdx.x;
    int i = blockIdx.x * 256 + t;
    s[t] = (i < NN) ? g_deg[i] : 0;
    __syncthreads();
    for (int off = 128; off > 0; off >>= 1) {
        if (t < off) s[t] += s[t + off];
        __syncthreads();
    }
    if (t == 0) g_bsum[blockIdx.x] = s[0];
}

__global__ void scan2_kernel() {
    __shared__ int s[512];
    int t = threadIdx.x;
    int v = (t < NB_SCAN) ? g_bsum[t] : 0;
    s[t] = v;
    __syncthreads();
    for (int off = 1; off < 512; off <<= 1) {
        int x = (t >= off) ? s[t - off] : 0;
        __syncthreads();
        s[t] += x;
        __syncthreads();
    }
    if (t < NB_SCAN) g_bsum[t] = s[t] - v;   // exclusive
}

__global__ void scan3_kernel() {
    __shared__ int s[256];
    int t = threadIdx.x;
    int i = blockIdx.x * 256 + t;
    int d = (i < NN) ? g_deg[i] : 0;
    s[t] = d;
    __syncthreads();
    for (int off = 1; off < 256; off <<= 1) {
        int x = (t >= off) ? s[t - off] : 0;
        __syncthreads();
        s[t] += x;
        __syncthreads();
    }
    int base = g_bsum[blockIdx.x];
    if (i < NN) {
        int excl = base + s[t] - d;
        g_rowptr[i] = excl;
        g_cursor[i] = excl;
        if (i == NN - 1) g_rowptr[NN] = base + s[t];
    }
}

// 4 edges per thread: 4 independent atomics + 4 scattered stores in flight
__global__ void scatter_kernel(const int* __restrict__ rows, const int* __restrict__ cols,
                               const float* __restrict__ vals, int nnz) {
    int base = (blockIdx.x * blockDim.x + threadIdx.x) * 4;
    if (base + 4 <= nnz) {
        int r0 = rows[base], r1 = rows[base + 1], r2 = rows[base + 2], r3 = rows[base + 3];
        int c0 = cols[base], c1 = cols[base + 1], c2 = cols[base + 2], c3 = cols[base + 3];
        float v0 = vals[base],     v1 = vals[base + 1];
        float v2 = vals[base + 2], v3 = vals[base + 3];
        int p0 = atomicAdd(&g_cursor[r0], 1);
        int p1 = atomicAdd(&g_cursor[r1], 1);
        int p2 = atomicAdd(&g_cursor[r2], 1);
        int p3 = atomicAdd(&g_cursor[r3], 1);
        g_edge[p0] = make_int2(c0, __float_as_int(v0));
        g_edge[p1] = make_int2(c1, __float_as_int(v1));
        g_edge[p2] = make_int2(c2, __float_as_int(v2));
        g_edge[p3] = make_int2(c3, __float_as_int(v3));
    } else {
        for (int e = base; e < nnz; e++) {
            int pos = atomicAdd(&g_cursor[rows[e]], 1);
            g_edge[pos] = make_int2(cols[e], __float_as_int(vals[e]));
        }
    }
}

// ---------------- fp32 -> fp16 convert (weights only) ----------------
__global__ void cvt_f2h_kernel(const float* __restrict__ src, __half* __restrict__ dst, int n4) {
    int i = blockIdx.x * blockDim.x + threadIdx.x;
    if (i < n4) {
        float4 v = *((const float4*)src + i);
        __half2 p0 = __floats2half2_rn(v.x, v.y);
        __half2 p1 = __floats2half2_rn(v.z, v.w);
        uint2 o; o.x = *(unsigned*)&p0; o.y = *(unsigned*)&p1;
        *((uint2*)dst + i) = o;
    }
}

// ---------------- tensor-core GEMM: G[N,DOUT](fp16) = A[N,128] @ W[128,DOUT](fp16) ----------------
__device__ __forceinline__ void mma16816(float* d, const unsigned* a, const unsigned* b) {
    asm volatile(
        "mma.sync.aligned.m16n8k16.row.col.f32.f16.f16.f32 "
        "{%0,%1,%2,%3}, {%4,%5,%6,%7}, {%8,%9}, {%0,%1,%2,%3};\n"
        : "+f"(d[0]), "+f"(d[1]), "+f"(d[2]), "+f"(d[3])
        : "r"(a[0]), "r"(a[1]), "r"(a[2]), "r"(a[3]),
          "r"(b[0]), "r"(b[1]));
}
__device__ __forceinline__ void ldsm_x4(unsigned* r, uint32_t addr) {
    asm volatile("ldmatrix.sync.aligned.m8n8.x4.shared.b16 {%0,%1,%2,%3}, [%4];\n"
        : "=r"(r[0]), "=r"(r[1]), "=r"(r[2]), "=r"(r[3]) : "r"(addr));
}
__device__ __forceinline__ void ldsm_x2_trans(unsigned* r, uint32_t addr) {
    asm volatile("ldmatrix.sync.aligned.m8n8.x2.trans.shared.b16 {%0,%1}, [%2];\n"
        : "=r"(r[0]), "=r"(r[1]) : "r"(addr));
}

// BM=128 rows/block, K chunked at BK=64; static smem. TIN = __half (pass-through)
// or float (fused fp32->fp16 convert during the A-tile smem store, used for layer 1's X).
template <int DOUT, typename TIN>
__global__ __launch_bounds__(256) void gemm_tc_kernel(const TIN* __restrict__ A,
                                                      const __half* __restrict__ W,
                                                      __half* __restrict__ G) {
    constexpr int BM = 128;
    constexpr int BK = 64;
    constexpr int APITCH_H = BK + 8;              // 72 halves = 144B (stride ≡ 4 banks)
    constexpr int WPITCH_H = DOUT + 8;            // 136 or 72 halves
    constexpr int WN = 32;
    constexpr int WM = (DOUT == 128) ? 64 : 32;
    constexpr int MT = WM / 16;
    constexpr int NT = WN / 8;

    __shared__ __half As[BM * APITCH_H];
    __shared__ __half Ws[BK * WPITCH_H];

    const int t = threadIdx.x;
    const int lane = t & 31;
    const int wid = t >> 5;
    const int warp_m = (DOUT == 128) ? (wid >> 2) : (wid >> 1);
    const int warp_n = (DOUT == 128) ? (wid & 3) : (wid & 1);
    const int row0 = blockIdx.x * BM;

    float acc[MT][NT][4];
#pragma unroll
    for (int i = 0; i < MT; i++)
#pragma unroll
        for (int j = 0; j < NT; j++) {
            acc[i][j][0] = 0.f; acc[i][j][1] = 0.f;
            acc[i][j][2] = 0.f; acc[i][j][3] = 0.f;
        }

    const uint32_t as_base = (uint32_t)__cvta_generic_to_shared(As);
    const uint32_t ws_base = (uint32_t)__cvta_generic_to_shared(Ws);

    for (int kc = 0; kc < 128; kc += BK) {
        // ---- load A tile (dtype-specialized) ----
        if constexpr (sizeof(TIN) == 2) {
            uint4* dst = (uint4*)As;
            constexpr int U4PR = BK / 8;          // 8 uint4 per row
#pragma unroll
            for (int s = t; s < BM * U4PR; s += 256) {
                int r = s / U4PR, c4 = s % U4PR;
                uint4 v = make_uint4(0, 0, 0, 0);
                int gr = row0 + r;
                if (gr < NN) v = *((const uint4*)((const __half*)A + (size_t)gr * 128 + kc) + c4);
                dst[r * (APITCH_H / 8) + c4] = v;
            }
        } else {
            // fp32 input: float4 (4 elems) -> half2 x2 -> 8B smem store
            constexpr int F4PR = BK / 4;          // 16 float4 per row
#pragma unroll
            for (int s = t; s < BM * F4PR; s += 256) {
                int r = s / F4PR, c4 = s % F4PR;
                float4 v = make_float4(0.f, 0.f, 0.f, 0.f);
                int gr = row0 + r;
                if (gr < NN) v = *((const float4*)((const float*)A + (size_t)gr * 128 + kc) + c4);
                __half2 p0 = __floats2half2_rn(v.x, v.y);
                __half2 p1 = __floats2half2_rn(v.z, v.w);
                uint2 o; o.x = *(unsigned*)&p0; o.y = *(unsigned*)&p1;
                *(uint2*)&As[r * APITCH_H + c4 * 4] = o;
            }
        }
        // ---- load W tile ----
        {
            constexpr int WU4 = DOUT / 8;
            uint4* dst = (uint4*)Ws;
#pragma unroll
            for (int s = t; s < BK * WU4; s += 256) {
                int r = s / WU4, c4 = s % WU4;
                dst[r * (WPITCH_H / 8) + c4] = *((const uint4*)(W + (size_t)(kc + r) * DOUT) + c4);
            }
        }
        __syncthreads();

#pragma unroll
        for (int k = 0; k < BK; k += 16) {
            unsigned afrag[MT][4];
            unsigned bfrag[NT][2];
#pragma unroll
            for (int mt = 0; mt < MT; mt++) {
                int row = warp_m * WM + mt * 16 + (lane & 15);
                int col = k + ((lane >> 4) << 3);
                ldsm_x4(afrag[mt], as_base + (row * APITCH_H + col) * 2);
            }
#pragma unroll
            for (int nt = 0; nt < NT; nt++) {
                int krow = k + (lane & 15);
                int col = warp_n * WN + nt * 8;
                ldsm_x2_trans(bfrag[nt], ws_base + (krow * WPITCH_H + col) * 2);
            }
#pragma unroll
            for (int mt = 0; mt < MT; mt++)
#pragma unroll
                for (int nt = 0; nt < NT; nt++)
                    mma16816(acc[mt][nt], afrag[mt], bfrag[nt]);
        }
        __syncthreads();
    }

    // epilogue: fp16 store
    const int gID = lane >> 2;
    const int tc = lane & 3;
#pragma unroll
    for (int mt = 0; mt < MT; mt++) {
#pragma unroll
        for (int nt = 0; nt < NT; nt++) {
            int col = warp_n * WN + nt * 8 + tc * 2;
            int r0 = row0 + warp_m * WM + mt * 16 + gID;
            if (r0 < NN) {
                __half2 p = __floats2half2_rn(acc[mt][nt][0], acc[mt][nt][1]);
                *(unsigned*)(G + (size_t)r0 * DOUT + col) = *(unsigned*)&p;
            }
            int r1 = r0 + 8;
            if (r1 < NN) {
                __half2 p = __floats2half2_rn(acc[mt][nt][2], acc[mt][nt][3]);
                *(unsigned*)(G + (size_t)r1 * DOUT + col) = *(unsigned*)&p;
            }
        }
    }
}

// ---------------- SpMM (CSR gather, fp16 in / fp16 out): H[r] = relu(sum val*G[col] + bias) ----------------
__global__ __launch_bounds__(256) void spmm128h_kernel(const __half* __restrict__ G,
                                                       const float* __restrict__ bias,
                                                       __half* __restrict__ out) {
    int r = (blockIdx.x * blockDim.x + threadIdx.x) >> 5;
    if (r >= NN) return;
    int lane = threadIdx.x & 31;
    int beg = g_rowptr[r], end = g_rowptr[r + 1];

    float4 acc = make_float4(0.f, 0.f, 0.f, 0.f);
    int e = beg;
#pragma unroll 1
    for (; e + 4 <= end; e += 4) {
        int2 e0 = g_edge[e];     int2 e1 = g_edge[e + 1];
        int2 e2 = g_edge[e + 2]; int2 e3 = g_edge[e + 3];
        uint2 qa = *((const uint2*)(G + (size_t)e0.x * 128) + lane);
        uint2 qb = *((const uint2*)(G + (size_t)e1.x * 128) + lane);
        uint2 qc = *((const uint2*)(G + (size_t)e2.x * 128) + lane);
        uint2 qd = *((const uint2*)(G + (size_t)e3.x * 128) + lane);
        float v0 = __int_as_float(e0.y), v1 = __int_as_float(e1.y);
        float v2 = __int_as_float(e2.y), v3 = __int_as_float(e3.y);
        float2 a0 = __half22float2(*(__half2*)&qa.x), a1 = __half22float2(*(__half2*)&qa.y);
        float2 b0 = __half22float2(*(__half2*)&qb.x), b1 = __half22float2(*(__half2*)&qb.y);
        float2 c0 = __half22float2(*(__half2*)&qc.x), c1 = __half22float2(*(__half2*)&qc.y);
        float2 d0 = __half22float2(*(__half2*)&qd.x), d1 = __half22float2(*(__half2*)&qd.y);
        acc.x += v0 * a0.x + v1 * b0.x + v2 * c0.x + v3 * d0.x;
        acc.y += v0 * a0.y + v1 * b0.y + v2 * c0.y + v3 * d0.y;
        acc.z += v0 * a1.x + v1 * b1.x + v2 * c1.x + v3 * d1.x;
        acc.w += v0 * a1.y + v1 * b1.y + v2 * c1.y + v3 * d1.y;
    }
#pragma unroll 1
    for (; e < end; e++) {
        int2 e0 = g_edge[e];
        float v0 = __int_as_float(e0.y);
        uint2 qa = *((const uint2*)(G + (size_t)e0.x * 128) + lane);
        float2 a0 = __half22float2(*(__half2*)&qa.x), a1 = __half22float2(*(__half2*)&qa.y);
        acc.x += v0 * a0.x; acc.y += v0 * a0.y;
        acc.z += v0 * a1.x; acc.w += v0 * a1.y;
    }
    float4 b4 = *((const float4*)bias + lane);
    acc.x = fmaxf(acc.x + b4.x, 0.f); acc.y = fmaxf(acc.y + b4.y, 0.f);
    acc.z = fmaxf(acc.z + b4.z, 0.f); acc.w = fmaxf(acc.w + b4.w, 0.f);
    __half2 p0 = __floats2half2_rn(acc.x, acc.y);
    __half2 p1 = __floats2half2_rn(acc.z, acc.w);
    uint2 o; o.x = *(unsigned*)&p0; o.y = *(unsigned*)&p1;
    *((uint2*)(out + (size_t)r * 128) + lane) = o;
}

// d=64 final layer: fp16 gather, fp32 out, no ReLU
__global__ __launch_bounds__(256) void spmm64_kernel(const __half* __restrict__ G,
                                                     const float* __restrict__ bias,
                                                     float* __restrict__ out) {
    int r = (blockIdx.x * blockDim.x + threadIdx.x) >> 5;
    if (r >= NN) return;
    int lane = threadIdx.x & 31;
    int beg = g_rowptr[r], end = g_rowptr[r + 1];

    float2 acc = make_float2(0.f, 0.f);
    int e = beg;
#pragma unroll 1
    for (; e + 4 <= end; e += 4) {
        int2 e0 = g_edge[e];     int2 e1 = g_edge[e + 1];
        int2 e2 = g_edge[e + 2]; int2 e3 = g_edge[e + 3];
        unsigned qa = *((const unsigned*)(G + (size_t)e0.x * 64) + lane);
        unsigned qb = *((const unsigned*)(G + (size_t)e1.x * 64) + lane);
        unsigned qc = *((const unsigned*)(G + (size_t)e2.x * 64) + lane);
        unsigned qd = *((const unsigned*)(G + (size_t)e3.x * 64) + lane);
        float v0 = __int_as_float(e0.y), v1 = __int_as_float(e1.y);
        float v2 = __int_as_float(e2.y), v3 = __int_as_float(e3.y);
        float2 a = __half22float2(*(__half2*)&qa);
        float2 b = __half22float2(*(__half2*)&qb);
        float2 c = __half22float2(*(__half2*)&qc);
        float2 d = __half22float2(*(__half2*)&qd);
        acc.x += v0 * a.x + v1 * b.x + v2 * c.x + v3 * d.x;
        acc.y += v0 * a.y + v1 * b.y + v2 * c.y + v3 * d.y;
    }
#pragma unroll 1
    for (; e < end; e++) {
        int2 e0 = g_edge[e];
        float v0 = __int_as_float(e0.y);
        unsigned qa = *((const unsigned*)(G + (size_t)e0.x * 64) + lane);
        float2 a = __half22float2(*(__half2*)&qa);
        acc.x += v0 * a.x; acc.y += v0 * a.y;
    }
    float2 b2 = *((const float2*)bias + lane);
    acc.x += b2.x; acc.y += b2.y;
    *((float2*)(out + (size_t)r * 64) + lane) = acc;
}

// ---------------- launch ----------------
extern "C" void kernel_launch(void* const* d_in, const int* in_sizes, int n_in,
                              void* d_out, int out_size) {
    (void)n_in; (void)out_size;
    const float* X    = (const float*)d_in[0];
    const int*   rows = (const int*)  d_in[1];
    const int*   cols = (const int*)  d_in[2];
    const float* vals = (const float*)d_in[3];
    const float* W1   = (const float*)d_in[4];
    const float* b1   = (const float*)d_in[5];
    const float* W2   = (const float*)d_in[6];
    const float* b2   = (const float*)d_in[7];
    const float* W3   = (const float*)d_in[8];
    const float* b3   = (const float*)d_in[9];
    float* out = (float*)d_out;
    const int nnz = in_sizes[1];

    __half *A = nullptr, *G = nullptr, *W1h = nullptr, *W2h = nullptr, *W3h = nullptr;
    cudaGetSymbolAddress((void**)&A, g_A);
    cudaGetSymbolAddress((void**)&G, g_G);
    cudaGetSymbolAddress((void**)&W1h, g_W1h);
    cudaGetSymbolAddress((void**)&W2h, g_W2h);
    cudaGetSymbolAddress((void**)&W3h, g_W3h);

    const int TB = 256;
    const int spmm_blocks = (NN + 7) / 8;
    const int gemm_blocks = (NN + 127) / 128;
    const int e4_blocks = (nnz + TB * 4 - 1) / (TB * 4);

    // CSR build (4-edge ILP on the atomic kernels)
    zero_deg_kernel<<<(NN + TB - 1) / TB, TB>>>();
    histo_kernel<<<e4_blocks, TB>>>(rows, nnz);
    scan1_kernel<<<NB_SCAN, 256>>>();
    scan2_kernel<<<1, 512>>>();
    scan3_kernel<<<NB_SCAN, 256>>>();
    scatter_kernel<<<e4_blocks, TB>>>(rows, cols, vals, nnz);

    // weight converts (tiny)
    cvt_f2h_kernel<<<(128 * 128 / 4 + TB - 1) / TB, TB>>>(W1, W1h, 128 * 128 / 4);
    cvt_f2h_kernel<<<(128 * 128 / 4 + TB - 1) / TB, TB>>>(W2, W2h, 128 * 128 / 4);
    cvt_f2h_kernel<<<(128 * 64 / 4 + TB - 1) / TB, TB>>>(W3, W3h, 128 * 64 / 4);

    // layer 1: G = fp16(X)@W1h (convert fused into GEMM) ; A = relu(A_norm G + b1)
    gemm_tc_kernel<128, float><<<gemm_blocks, TB>>>(X, W1h, G);
    spmm128h_kernel<<<spmm_blocks, TB>>>(G, b1, A);

    // layer 2
    gemm_tc_kernel<128, __half><<<gemm_blocks, TB>>>(A, W2h, G);
    spmm128h_kernel<<<spmm_blocks, TB>>>(G, b2, A);

    // layer 3 (64-wide), fp32 output
    gemm_tc_kernel<64, __half><<<gemm_blocks, TB>>>(A, W3h, G);
    spmm64_kernel<<<spmm_blocks, TB>>>(G, b3, out);
}

// round 9
// speedup vs baseline: 2.1449x; 1.0185x over previous
#include <cuda_runtime.h>
#include <cuda_fp16.h>
#include <cstddef>
#include <cstdint>

#define NN 100000
#define NNZ_MAX 3300000
#define NB_SCAN 391              // ceil(NN/256)

// ---------------- scratch (static device globals; no allocation) ----------------
__device__ int    g_deg[NN];
__device__ int    g_cursor[NN];
__device__ int    g_rowptr[NN + 1];
__device__ int    g_bsum[512];
__device__ int2   g_edge[NNZ_MAX];               // {col, val as int-bits}
__device__ __half g_A[(size_t)NN * 128];         // fp16 H buffer (SpMM output / GEMM input)
__device__ __half g_G[(size_t)NN * 128];         // fp16 GEMM output (SpMM gather operand)
__device__ __half g_W1h[128 * 128];
__device__ __half g_W2h[128 * 128];
__device__ __half g_W3h[128 * 64];

// ---------------- prep: zero deg + convert all weights (one kernel) ----------------
__global__ void prep_kernel(const float* __restrict__ W1, const float* __restrict__ W2,
                            const float* __restrict__ W3) {
    int b = blockIdx.x, t = threadIdx.x;
    if (b < NB_SCAN) {                                  // zero g_deg
        int i = b * 256 + t;
        if (i < NN) g_deg[i] = 0;
    } else if (b < NB_SCAN + 16) {                      // W1: 16384 elems = 4096 float4
        int i = (b - NB_SCAN) * 256 + t;
        float4 v = ((const float4*)W1)[i];
        __half2 p0 = __floats2half2_rn(v.x, v.y);
        __half2 p1 = __floats2half2_rn(v.z, v.w);
        uint2 o; o.x = *(unsigned*)&p0; o.y = *(unsigned*)&p1;
        ((uint2*)g_W1h)[i] = o;
    } else if (b < NB_SCAN + 32) {                      // W2
        int i = (b - NB_SCAN - 16) * 256 + t;
        float4 v = ((const float4*)W2)[i];
        __half2 p0 = __floats2half2_rn(v.x, v.y);
        __half2 p1 = __floats2half2_rn(v.z, v.w);
        uint2 o; o.x = *(unsigned*)&p0; o.y = *(unsigned*)&p1;
        ((uint2*)g_W2h)[i] = o;
    } else {                                            // W3: 8192 elems = 2048 float4
        int i = (b - NB_SCAN - 32) * 256 + t;
        if (i < 2048) {
            float4 v = ((const float4*)W3)[i];
            __half2 p0 = __floats2half2_rn(v.x, v.y);
            __half2 p1 = __floats2half2_rn(v.z, v.w);
            uint2 o; o.x = *(unsigned*)&p0; o.y = *(unsigned*)&p1;
            ((uint2*)g_W3h)[i] = o;
        }
    }
}

// ---------------- CSR build ----------------
__global__ void histo_kernel(const int* __restrict__ rows, int nnz) {
    int base = (blockIdx.x * blockDim.x + threadIdx.x) * 4;
    if (base + 4 <= nnz) {
        int r0 = rows[base], r1 = rows[base + 1], r2 = rows[base + 2], r3 = rows[base + 3];
        atomicAdd(&g_deg[r0], 1);
        atomicAdd(&g_deg[r1], 1);
        atomicAdd(&g_deg[r2], 1);
        atomicAdd(&g_deg[r3], 1);
    } else {
        for (int e = base; e < nnz; e++) atomicAdd(&g_deg[rows[e]], 1);
    }
}

__global__ void scan1_kernel() {
    __shared__ int s[256];
    int t = threadIdx.x;
    int i = blockIdx.x * 256 + t;
    s[t] = (i < NN) ? g_deg[i] : 0;
    __syncthreads();
    for (int off = 128; off > 0; off >>= 1) {
        if (t < off) s[t] += s[t + off];
        __syncthreads();
    }
    if (t == 0) g_bsum[blockIdx.x] = s[0];
}

__global__ void scan2_kernel() {
    __shared__ int s[512];
    int t = threadIdx.x;
    int v = (t < NB_SCAN) ? g_bsum[t] : 0;
    s[t] = v;
    __syncthreads();
    for (int off = 1; off < 512; off <<= 1) {
        int x = (t >= off) ? s[t - off] : 0;
        __syncthreads();
        s[t] += x;
        __syncthreads();
    }
    if (t < NB_SCAN) g_bsum[t] = s[t] - v;   // exclusive
}

__global__ void scan3_kernel() {
    __shared__ int s[256];
    int t = threadIdx.x;
    int i = blockIdx.x * 256 + t;
    int d = (i < NN) ? g_deg[i] : 0;
    s[t] = d;
    __syncthreads();
    for (int off = 1; off < 256; off <<= 1) {
        int x = (t >= off) ? s[t - off] : 0;
        __syncthreads();
        s[t] += x;
        __syncthreads();
    }
    int base = g_bsum[blockIdx.x];
    if (i < NN) {
        int excl = base + s[t] - d;
        g_rowptr[i] = excl;
        g_cursor[i] = excl;
        if (i == NN - 1) g_rowptr[NN] = base + s[t];
    }
}

__global__ void scatter_kernel(const int* __restrict__ rows, const int* __restrict__ cols,
                               const float* __restrict__ vals, int nnz) {
    int base = (blockIdx.x * blockDim.x + threadIdx.x) * 4;
    if (base + 4 <= nnz) {
        int r0 = rows[base], r1 = rows[base + 1], r2 = rows[base + 2], r3 = rows[base + 3];
        int c0 = cols[base], c1 = cols[base + 1], c2 = cols[base + 2], c3 = cols[base + 3];
        float v0 = vals[base],     v1 = vals[base + 1];
        float v2 = vals[base + 2], v3 = vals[base + 3];
        int p0 = atomicAdd(&g_cursor[r0], 1);
        int p1 = atomicAdd(&g_cursor[r1], 1);
        int p2 = atomicAdd(&g_cursor[r2], 1);
        int p3 = atomicAdd(&g_cursor[r3], 1);
        g_edge[p0] = make_int2(c0, __float_as_int(v0));
        g_edge[p1] = make_int2(c1, __float_as_int(v1));
        g_edge[p2] = make_int2(c2, __float_as_int(v2));
        g_edge[p3] = make_int2(c3, __float_as_int(v3));
    } else {
        for (int e = base; e < nnz; e++) {
            int pos = atomicAdd(&g_cursor[rows[e]], 1);
            g_edge[pos] = make_int2(cols[e], __float_as_int(vals[e]));
        }
    }
}

// ---------------- mma / ldmatrix / cp.async helpers ----------------
__device__ __forceinline__ void mma16816(float* d, const unsigned* a, const unsigned* b) {
    asm volatile(
        "mma.sync.aligned.m16n8k16.row.col.f32.f16.f16.f32 "
        "{%0,%1,%2,%3}, {%4,%5,%6,%7}, {%8,%9}, {%0,%1,%2,%3};\n"
        : "+f"(d[0]), "+f"(d[1]), "+f"(d[2]), "+f"(d[3])
        : "r"(a[0]), "r"(a[1]), "r"(a[2]), "r"(a[3]),
          "r"(b[0]), "r"(b[1]));
}
__device__ __forceinline__ void ldsm_x4(unsigned* r, uint32_t addr) {
    asm volatile("ldmatrix.sync.aligned.m8n8.x4.shared.b16 {%0,%1,%2,%3}, [%4];\n"
        : "=r"(r[0]), "=r"(r[1]), "=r"(r[2]), "=r"(r[3]) : "r"(addr));
}
__device__ __forceinline__ void ldsm_x2_trans(unsigned* r, uint32_t addr) {
    asm volatile("ldmatrix.sync.aligned.m8n8.x2.trans.shared.b16 {%0,%1}, [%2];\n"
        : "=r"(r[0]), "=r"(r[1]) : "r"(addr));
}
__device__ __forceinline__ void cp_async16(uint32_t dst, const void* src, int src_bytes) {
    asm volatile("cp.async.cg.shared.global [%0], [%1], 16, %2;\n"
        :: "r"(dst), "l"(src), "r"(src_bytes));
}
__device__ __forceinline__ void cp_commit() {
    asm volatile("cp.async.commit_group;\n" ::: "memory");
}
template <int N>
__device__ __forceinline__ void cp_wait() {
    asm volatile("cp.async.wait_group %0;\n" :: "n"(N) : "memory");
}

// ---------------- pipelined tensor-core GEMM (fp16 in): G = A @ W ----------------
// BM=128, BK=32 (4 chunks), 2-stage cp.async double buffer, static smem.
template <int DOUT>
__global__ __launch_bounds__(256) void gemm_tc_async(const __half* __restrict__ A,
                                                     const __half* __restrict__ W,
                                                     __half* __restrict__ G) {
    constexpr int BM = 128;
    constexpr int BK = 32;
    constexpr int NC = 128 / BK;                  // 4 chunks
    constexpr int AP = BK + 8;                    // 40 halves = 80B pitch (conflict-free ldmatrix)
    constexpr int WP = DOUT + 8;                  // 136 / 72 halves
    constexpr int WN = 32;
    constexpr int WM = (DOUT == 128) ? 64 : 32;
    constexpr int MT = WM / 16;
    constexpr int NT = WN / 8;

    __shared__ __half As[2][BM * AP];             // 2 x 10240 B
    __shared__ __half Ws[2][BK * WP];             // 2 x 8704 B (DOUT=128) / 2 x 4608 B

    const int t = threadIdx.x;
    const int lane = t & 31;
    const int wid = t >> 5;
    const int warp_m = (DOUT == 128) ? (wid >> 2) : (wid >> 1);
    const int warp_n = (DOUT == 128) ? (wid & 3) : (wid & 1);
    const int row0 = blockIdx.x * BM;

    const uint32_t asb[2] = { (uint32_t)__cvta_generic_to_shared(&As[0][0]),
                              (uint32_t)__cvta_generic_to_shared(&As[1][0]) };
    const uint32_t wsb[2] = { (uint32_t)__cvta_generic_to_shared(&Ws[0][0]),
                              (uint32_t)__cvta_generic_to_shared(&Ws[1][0]) };

    auto issue_chunk = [&](int c, int st) {
        const int kc = c * BK;
        // A: 128 rows x 64B = 512 x 16B
#pragma unroll
        for (int s = t; s < BM * 4; s += 256) {
            int r = s >> 2, q = s & 3;
            int gr = row0 + r;
            const __half* src = A + (size_t)(gr < NN ? gr : 0) * 128 + kc + q * 8;
            cp_async16(asb[st] + (r * AP + q * 8) * 2, src, gr < NN ? 16 : 0);
        }
        // W: BK rows x DOUT*2 B
        constexpr int WQ = DOUT / 8;              // 16B pieces per row
#pragma unroll
        for (int s = t; s < BK * WQ; s += 256) {
            int r = s / WQ, q = s % WQ;
            cp_async16(wsb[st] + (r * WP + q * 8) * 2,
                       W + (size_t)(kc + r) * DOUT + q * 8, 16);
        }
        cp_commit();
    };

    float acc[MT][NT][4];
#pragma unroll
    for (int i = 0; i < MT; i++)
#pragma unroll
        for (int j = 0; j < NT; j++) {
            acc[i][j][0] = 0.f; acc[i][j][1] = 0.f;
            acc[i][j][2] = 0.f; acc[i][j][3] = 0.f;
        }

    issue_chunk(0, 0);

#pragma unroll
    for (int c = 0; c < NC; c++) {
        if (c + 1 < NC) {
            issue_chunk(c + 1, (c + 1) & 1);
            cp_wait<1>();
        } else {
            cp_wait<0>();
        }
        __syncthreads();

        const int st = c & 1;
#pragma unroll
        for (int k = 0; k < BK; k += 16) {
            unsigned afrag[MT][4];
            unsigned bfrag[NT][2];
#pragma unroll
            for (int mt = 0; mt < MT; mt++) {
                int row = warp_m * WM + mt * 16 + (lane & 15);
                int col = k + ((lane >> 4) << 3);
                ldsm_x4(afrag[mt], asb[st] + (row * AP + col) * 2);
            }
#pragma unroll
            for (int nt = 0; nt < NT; nt++) {
                int krow = k + (lane & 15);
                int col = warp_n * WN + nt * 8;
                ldsm_x2_trans(bfrag[nt], wsb[st] + (krow * WP + col) * 2);
            }
#pragma unroll
            for (int mt = 0; mt < MT; mt++)
#pragma unroll
                for (int nt = 0; nt < NT; nt++)
                    mma16816(acc[mt][nt], afrag[mt], bfrag[nt]);
        }
        __syncthreads();   // protect stage buffer before next issue overwrites it
    }

    // epilogue: fp16 store
    const int gID = lane >> 2;
    const int tc = lane & 3;
#pragma unroll
    for (int mt = 0; mt < MT; mt++) {
#pragma unroll
        for (int nt = 0; nt < NT; nt++) {
            int col = warp_n * WN + nt * 8 + tc * 2;
            int r0 = row0 + warp_m * WM + mt * 16 + gID;
            if (r0 < NN) {
                __half2 p = __floats2half2_rn(acc[mt][nt][0], acc[mt][nt][1]);
                *(unsigned*)(G + (size_t)r0 * DOUT + col) = *(unsigned*)&p;
            }
            int r1 = r0 + 8;
            if (r1 < NN) {
                __half2 p = __floats2half2_rn(acc[mt][nt][2], acc[mt][nt][3]);
                *(unsigned*)(G + (size_t)r1 * DOUT + col) = *(unsigned*)&p;
            }
        }
    }
}

// ---------------- layer-1 GEMM (fp32 in, fused convert; non-pipelined, BK=64) ----------------
__global__ __launch_bounds__(256) void gemm_tc_f32(const float* __restrict__ A,
                                                   const __half* __restrict__ W,
                                                   __half* __restrict__ G) {
    constexpr int DOUT = 128;
    constexpr int BM = 128;
    constexpr int BK = 64;
    constexpr int AP = BK + 8;                    // 72
    constexpr int WP = DOUT + 8;                  // 136
    constexpr int WN = 32, WM = 64, MT = 4, NT = 4;

    __shared__ __half As[BM * AP];
    __shared__ __half Ws[BK * WP];

    const int t = threadIdx.x;
    const int lane = t & 31;
    const int wid = t >> 5;
    const int warp_m = wid >> 2;
    const int warp_n = wid & 3;
    const int row0 = blockIdx.x * BM;

    float acc[MT][NT][4];
#pragma unroll
    for (int i = 0; i < MT; i++)
#pragma unroll
        for (int j = 0; j < NT; j++) {
            acc[i][j][0] = 0.f; acc[i][j][1] = 0.f;
            acc[i][j][2] = 0.f; acc[i][j][3] = 0.f;
        }

    const uint32_t as_base = (uint32_t)__cvta_generic_to_shared(As);
    const uint32_t ws_base = (uint32_t)__cvta_generic_to_shared(Ws);

    for (int kc = 0; kc < 128; kc += BK) {
        constexpr int F4PR = BK / 4;              // 16 float4 per row
#pragma unroll
        for (int s = t; s < BM * F4PR; s += 256) {
            int r = s / F4PR, c4 = s % F4PR;
            float4 v = make_float4(0.f, 0.f, 0.f, 0.f);
            int gr = row0 + r;
            if (gr < NN) v = *((const float4*)(A + (size_t)gr * 128 + kc) + c4);
            __half2 p0 = __floats2half2_rn(v.x, v.y);
            __half2 p1 = __floats2half2_rn(v.z, v.w);
            uint2 o; o.x = *(unsigned*)&p0; o.y = *(unsigned*)&p1;
            *(uint2*)&As[r * AP + c4 * 4] = o;
        }
        constexpr int WU4 = DOUT / 8;
        uint4* dst = (uint4*)Ws;
#pragma unroll
        for (int s = t; s < BK * WU4; s += 256) {
            int r = s / WU4, c4 = s % WU4;
            dst[r * (WP / 8) + c4] = *((const uint4*)(W + (size_t)(kc + r) * DOUT) + c4);
        }
        __syncthreads();

#pragma unroll
        for (int k = 0; k < BK; k += 16) {
            unsigned afrag[MT][4];
            unsigned bfrag[NT][2];
#pragma unroll
            for (int mt = 0; mt < MT; mt++) {
                int row = warp_m * WM + mt * 16 + (lane & 15);
                int col = k + ((lane >> 4) << 3);
                ldsm_x4(afrag[mt], as_base + (row * AP + col) * 2);
            }
#pragma unroll
            for (int nt = 0; nt < NT; nt++) {
                int krow = k + (lane & 15);
                int col = warp_n * WN + nt * 8;
                ldsm_x2_trans(bfrag[nt], ws_base + (krow * WP + col) * 2);
            }
#pragma unroll
            for (int mt = 0; mt < MT; mt++)
#pragma unroll
                for (int nt = 0; nt < NT; nt++)
                    mma16816(acc[mt][nt], afrag[mt], bfrag[nt]);
        }
        __syncthreads();
    }

    const int gID = lane >> 2;
    const int tc = lane & 3;
#pragma unroll
    for (int mt = 0; mt < MT; mt++) {
#pragma unroll
        for (int nt = 0; nt < NT; nt++) {
            int col = warp_n * WN + nt * 8 + tc * 2;
            int r0 = row0 + warp_m * WM + mt * 16 + gID;
            if (r0 < NN) {
                __half2 p = __floats2half2_rn(acc[mt][nt][0], acc[mt][nt][1]);
                *(unsigned*)(G + (size_t)r0 * DOUT + col) = *(unsigned*)&p;
            }
            int r1 = r0 + 8;
            if (r1 < NN) {
                __half2 p = __floats2half2_rn(acc[mt][nt][2], acc[mt][nt][3]);
                *(unsigned*)(G + (size_t)r1 * DOUT + col) = *(unsigned*)&p;
            }
        }
    }
}

// ---------------- SpMM (CSR gather, fp16 in / fp16 out): H[r] = relu(sum val*G[col] + bias) ----------------
__global__ __launch_bounds__(256) void spmm128h_kernel(const __half* __restrict__ G,
                                                       const float* __restrict__ bias,
                                                       __half* __restrict__ out) {
    int r = (blockIdx.x * blockDim.x + threadIdx.x) >> 5;
    if (r >= NN) return;
    int lane = threadIdx.x & 31;
    int beg = g_rowptr[r], end = g_rowptr[r + 1];

    float4 acc = make_float4(0.f, 0.f, 0.f, 0.f);
    int e = beg;
#pragma unroll 1
    for (; e + 4 <= end; e += 4) {
        int2 e0 = g_edge[e];     int2 e1 = g_edge[e + 1];
        int2 e2 = g_edge[e + 2]; int2 e3 = g_edge[e + 3];
        uint2 qa = *((const uint2*)(G + (size_t)e0.x * 128) + lane);
        uint2 qb = *((const uint2*)(G + (size_t)e1.x * 128) + lane);
        uint2 qc = *((const uint2*)(G + (size_t)e2.x * 128) + lane);
        uint2 qd = *((const uint2*)(G + (size_t)e3.x * 128) + lane);
        float v0 = __int_as_float(e0.y), v1 = __int_as_float(e1.y);
        float v2 = __int_as_float(e2.y), v3 = __int_as_float(e3.y);
        float2 a0 = __half22float2(*(__half2*)&qa.x), a1 = __half22float2(*(__half2*)&qa.y);
        float2 b0 = __half22float2(*(__half2*)&qb.x), b1 = __half22float2(*(__half2*)&qb.y);
        float2 c0 = __half22float2(*(__half2*)&qc.x), c1 = __half22float2(*(__half2*)&qc.y);
        float2 d0 = __half22float2(*(__half2*)&qd.x), d1 = __half22float2(*(__half2*)&qd.y);
        acc.x += v0 * a0.x + v1 * b0.x + v2 * c0.x + v3 * d0.x;
        acc.y += v0 * a0.y + v1 * b0.y + v2 * c0.y + v3 * d0.y;
        acc.z += v0 * a1.x + v1 * b1.x + v2 * c1.x + v3 * d1.x;
        acc.w += v0 * a1.y + v1 * b1.y + v2 * c1.y + v3 * d1.y;
    }
#pragma unroll 1
    for (; e < end; e++) {
        int2 e0 = g_edge[e];
        float v0 = __int_as_float(e0.y);
        uint2 qa = *((const uint2*)(G + (size_t)e0.x * 128) + lane);
        float2 a0 = __half22float2(*(__half2*)&qa.x), a1 = __half22float2(*(__half2*)&qa.y);
        acc.x += v0 * a0.x; acc.y += v0 * a0.y;
        acc.z += v0 * a1.x; acc.w += v0 * a1.y;
    }
    float4 b4 = *((const float4*)bias + lane);
    acc.x = fmaxf(acc.x + b4.x, 0.f); acc.y = fmaxf(acc.y + b4.y, 0.f);
    acc.z = fmaxf(acc.z + b4.z, 0.f); acc.w = fmaxf(acc.w + b4.w, 0.f);
    __half2 p0 = __floats2half2_rn(acc.x, acc.y);
    __half2 p1 = __floats2half2_rn(acc.z, acc.w);
    uint2 o; o.x = *(unsigned*)&p0; o.y = *(unsigned*)&p1;
    *((uint2*)(out + (size_t)r * 128) + lane) = o;
}

__global__ __launch_bounds__(256) void spmm64_kernel(const __half* __restrict__ G,
                                                     const float* __restrict__ bias,
                                                     float* __restrict__ out) {
    int r = (blockIdx.x * blockDim.x + threadIdx.x) >> 5;
    if (r >= NN) return;
    int lane = threadIdx.x & 31;
    int beg = g_rowptr[r], end = g_rowptr[r + 1];

    float2 acc = make_float2(0.f, 0.f);
    int e = beg;
#pragma unroll 1
    for (; e + 4 <= end; e += 4) {
        int2 e0 = g_edge[e];     int2 e1 = g_edge[e + 1];
        int2 e2 = g_edge[e + 2]; int2 e3 = g_edge[e + 3];
        unsigned qa = *((const unsigned*)(G + (size_t)e0.x * 64) + lane);
        unsigned qb = *((const unsigned*)(G + (size_t)e1.x * 64) + lane);
        unsigned qc = *((const unsigned*)(G + (size_t)e2.x * 64) + lane);
        unsigned qd = *((const unsigned*)(G + (size_t)e3.x * 64) + lane);
        float v0 = __int_as_float(e0.y), v1 = __int_as_float(e1.y);
        float v2 = __int_as_float(e2.y), v3 = __int_as_float(e3.y);
        float2 a = __half22float2(*(__half2*)&qa);
        float2 b = __half22float2(*(__half2*)&qb);
        float2 c = __half22float2(*(__half2*)&qc);
        float2 d = __half22float2(*(__half2*)&qd);
        acc.x += v0 * a.x + v1 * b.x + v2 * c.x + v3 * d.x;
        acc.y += v0 * a.y + v1 * b.y + v2 * c.y + v3 * d.y;
    }
#pragma unroll 1
    for (; e < end; e++) {
        int2 e0 = g_edge[e];
        float v0 = __int_as_float(e0.y);
        unsigned qa = *((const unsigned*)(G + (size_t)e0.x * 64) + lane);
        float2 a = __half22float2(*(__half2*)&qa);
        acc.x += v0 * a.x; acc.y += v0 * a.y;
    }
    float2 b2 = *((const float2*)bias + lane);
    acc.x += b2.x; acc.y += b2.y;
    *((float2*)(out + (size_t)r * 64) + lane) = acc;
}

// ---------------- launch ----------------
extern "C" void kernel_launch(void* const* d_in, const int* in_sizes, int n_in,
                              void* d_out, int out_size) {
    (void)n_in; (void)out_size;
    const float* X    = (const float*)d_in[0];
    const int*   rows = (const int*)  d_in[1];
    const int*   cols = (const int*)  d_in[2];
    const float* vals = (const float*)d_in[3];
    const float* W1   = (const float*)d_in[4];
    const float* b1   = (const float*)d_in[5];
    const float* W2   = (const float*)d_in[6];
    const float* b2   = (const float*)d_in[7];
    const float* W3   = (const float*)d_in[8];
    const float* b3   = (const float*)d_in[9];
    float* out = (float*)d_out;
    const int nnz = in_sizes[1];

    __half *A = nullptr, *G = nullptr, *W1h = nullptr, *W2h = nullptr, *W3h = nullptr;
    cudaGetSymbolAddress((void**)&A, g_A);
    cudaGetSymbolAddress((void**)&G, g_G);
    cudaGetSymbolAddress((void**)&W1h, g_W1h);
    cudaGetSymbolAddress((void**)&W2h, g_W2h);
    cudaGetSymbolAddress((void**)&W3h, g_W3h);

    const int TB = 256;
    const int spmm_blocks = (NN + 7) / 8;
    const int gemm_blocks = (NN + 127) / 128;
    const int e4_blocks = (nnz + TB * 4 - 1) / (TB * 4);

    // prep: zero deg + all weight converts in one kernel
    prep_kernel<<<NB_SCAN + 32 + 8, TB>>>(W1, W2, W3);

    // CSR build
    histo_kernel<<<e4_blocks, TB>>>(rows, nnz);
    scan1_kernel<<<NB_SCAN, 256>>>();
    scan2_kernel<<<1, 512>>>();
    scan3_kernel<<<NB_SCAN, 256>>>();
    scatter_kernel<<<e4_blocks, TB>>>(rows, cols, vals, nnz);

    // layer 1: G = fp16(X)@W1h ; A = relu(A_norm G + b1)
    gemm_tc_f32<<<gemm_blocks, TB>>>(X, W1h, G);
    spmm128h_kernel<<<spmm_blocks, TB>>>(G, b1, A);

    // layer 2 (pipelined GEMM)
    gemm_tc_async<128><<<gemm_blocks, TB>>>(A, W2h, G);
    spmm128h_kernel<<<spmm_blocks, TB>>>(G, b2, A);

    // layer 3 (64-wide, pipelined), fp32 output
    gemm_tc_async<64><<<gemm_blocks, TB>>>(A, W3h, G);
    spmm64_kernel<<<spmm_blocks, TB>>>(G, b3, out);
}

// round 10
// speedup vs baseline: 2.2091x; 1.0299x over previous
#include <cuda_runtime.h>
#include <cuda_fp16.h>
#include <cstddef>
#include <cstdint>

#define NN 100000
#define NNZ_MAX 3300000
#define NB_Z 391                 // ceil(NN/256)  (prep zeroing blocks)
#define NB2 196                  // ceil(NN/512)  (scan blocks)

// ---------------- scratch (static device globals; no allocation) ----------------
__device__ int    g_deg[NN];
__device__ int    g_cursor[NN];
__device__ int    g_rowptr[NN + 1];
__device__ int    g_bsum[512];
__device__ int2   g_edge[NNZ_MAX];               // {col, val as int-bits}
__device__ __half g_A[(size_t)NN * 128];         // fp16 H buffer (SpMM output / GEMM input)
__device__ __half g_G[(size_t)NN * 128];         // fp16 GEMM output (SpMM gather operand)
__device__ __half g_W1h[128 * 128];
__device__ __half g_W2h[128 * 128];
__device__ __half g_W3h[128 * 64];

// ---------------- host-side stream/event objects (created once; host objects only) ----
static cudaStream_t g_side   = nullptr;
static cudaEvent_t  g_ev_fork = nullptr, g_ev_join = nullptr;
namespace {
struct StreamInit {
    StreamInit() {
        cudaStreamCreateWithFlags(&g_side, cudaStreamNonBlocking);
        cudaEventCreateWithFlags(&g_ev_fork, cudaEventDisableTiming);
        cudaEventCreateWithFlags(&g_ev_join, cudaEventDisableTiming);
    }
};
StreamInit s_stream_init;
}

// ---------------- prep: zero deg + convert all weights (one kernel) ----------------
__global__ void prep_kernel(const float* __restrict__ W1, const float* __restrict__ W2,
                            const float* __restrict__ W3) {
    int b = blockIdx.x, t = threadIdx.x;
    if (b < NB_Z) {                                     // zero g_deg
        int i = b * 256 + t;
        if (i < NN) g_deg[i] = 0;
    } else if (b < NB_Z + 16) {                         // W1: 4096 float4
        int i = (b - NB_Z) * 256 + t;
        float4 v = ((const float4*)W1)[i];
        __half2 p0 = __floats2half2_rn(v.x, v.y);
        __half2 p1 = __floats2half2_rn(v.z, v.w);
        uint2 o; o.x = *(unsigned*)&p0; o.y = *(unsigned*)&p1;
        ((uint2*)g_W1h)[i] = o;
    } else if (b < NB_Z + 32) {                         // W2
        int i = (b - NB_Z - 16) * 256 + t;
        float4 v = ((const float4*)W2)[i];
        __half2 p0 = __floats2half2_rn(v.x, v.y);
        __half2 p1 = __floats2half2_rn(v.z, v.w);
        uint2 o; o.x = *(unsigned*)&p0; o.y = *(unsigned*)&p1;
        ((uint2*)g_W2h)[i] = o;
    } else {                                            // W3: 2048 float4
        int i = (b - NB_Z - 32) * 256 + t;
        if (i < 2048) {
            float4 v = ((const float4*)W3)[i];
            __half2 p0 = __floats2half2_rn(v.x, v.y);
            __half2 p1 = __floats2half2_rn(v.z, v.w);
            uint2 o; o.x = *(unsigned*)&p0; o.y = *(unsigned*)&p1;
            ((uint2*)g_W3h)[i] = o;
        }
    }
}

// ---------------- CSR build ----------------
__global__ void histo_kernel(const int* __restrict__ rows, int nnz) {
    int base = (blockIdx.x * blockDim.x + threadIdx.x) * 4;
    if (base + 4 <= nnz) {
        int r0 = rows[base], r1 = rows[base + 1], r2 = rows[base + 2], r3 = rows[base + 3];
        atomicAdd(&g_deg[r0], 1);
        atomicAdd(&g_deg[r1], 1);
        atomicAdd(&g_deg[r2], 1);
        atomicAdd(&g_deg[r3], 1);
    } else {
        for (int e = base; e < nnz; e++) atomicAdd(&g_deg[rows[e]], 1);
    }
}

// per-block (512-wide) sums of deg
__global__ void scan1_kernel() {
    __shared__ int s[512];
    int t = threadIdx.x;
    int i = blockIdx.x * 512 + t;
    s[t] = (i < NN) ? g_deg[i] : 0;
    __syncthreads();
    for (int off = 256; off > 0; off >>= 1) {
        if (t < off) s[t] += s[t + off];
        __syncthreads();
    }
    if (t == 0) g_bsum[blockIdx.x] = s[0];
}

// fused: block-scan of the 196 block sums (redundant per block) + local scan + apply
__global__ void scan3_kernel() {
    __shared__ int bs[512];
    __shared__ int s[512];
    int t = threadIdx.x;

    // inclusive scan of g_bsum[0..NB2)
    bs[t] = (t < NB2) ? g_bsum[t] : 0;
    __syncthreads();
    for (int off = 1; off < 512; off <<= 1) {
        int x = (t >= off) ? bs[t - off] : 0;
        __syncthreads();
        bs[t] += x;
        __syncthreads();
    }
    int base = (blockIdx.x == 0) ? 0 : bs[blockIdx.x - 1];

    // local inclusive scan of this block's 512 deg values
    int i = blockIdx.x * 512 + t;
    int d = (i < NN) ? g_deg[i] : 0;
    s[t] = d;
    __syncthreads();
    for (int off = 1; off < 512; off <<= 1) {
        int x = (t >= off) ? s[t - off] : 0;
        __syncthreads();
        s[t] += x;
        __syncthreads();
    }
    if (i < NN) {
        int excl = base + s[t] - d;
        g_rowptr[i] = excl;
        g_cursor[i] = excl;
        if (i == NN - 1) g_rowptr[NN] = base + s[t];
    }
}

__global__ void scatter_kernel(const int* __restrict__ rows, const int* __restrict__ cols,
                               const float* __restrict__ vals, int nnz) {
    int base = (blockIdx.x * blockDim.x + threadIdx.x) * 4;
    if (base + 4 <= nnz) {
        int r0 = rows[base], r1 = rows[base + 1], r2 = rows[base + 2], r3 = rows[base + 3];
        int c0 = cols[base], c1 = cols[base + 1], c2 = cols[base + 2], c3 = cols[base + 3];
        float v0 = vals[base],     v1 = vals[base + 1];
        float v2 = vals[base + 2], v3 = vals[base + 3];
        int p0 = atomicAdd(&g_cursor[r0], 1);
        int p1 = atomicAdd(&g_cursor[r1], 1);
        int p2 = atomicAdd(&g_cursor[r2], 1);
        int p3 = atomicAdd(&g_cursor[r3], 1);
        g_edge[p0] = make_int2(c0, __float_as_int(v0));
        g_edge[p1] = make_int2(c1, __float_as_int(v1));
        g_edge[p2] = make_int2(c2, __float_as_int(v2));
        g_edge[p3] = make_int2(c3, __float_as_int(v3));
    } else {
        for (int e = base; e < nnz; e++) {
            int pos = atomicAdd(&g_cursor[rows[e]], 1);
            g_edge[pos] = make_int2(cols[e], __float_as_int(vals[e]));
        }
    }
}

// ---------------- mma / ldmatrix / cp.async helpers ----------------
__device__ __forceinline__ void mma16816(float* d, const unsigned* a, const unsigned* b) {
    asm volatile(
        "mma.sync.aligned.m16n8k16.row.col.f32.f16.f16.f32 "
        "{%0,%1,%2,%3}, {%4,%5,%6,%7}, {%8,%9}, {%0,%1,%2,%3};\n"
        : "+f"(d[0]), "+f"(d[1]), "+f"(d[2]), "+f"(d[3])
        : "r"(a[0]), "r"(a[1]), "r"(a[2]), "r"(a[3]),
          "r"(b[0]), "r"(b[1]));
}
__device__ __forceinline__ void ldsm_x4(unsigned* r, uint32_t addr) {
    asm volatile("ldmatrix.sync.aligned.m8n8.x4.shared.b16 {%0,%1,%2,%3}, [%4];\n"
        : "=r"(r[0]), "=r"(r[1]), "=r"(r[2]), "=r"(r[3]) : "r"(addr));
}
__device__ __forceinline__ void ldsm_x2_trans(unsigned* r, uint32_t addr) {
    asm volatile("ldmatrix.sync.aligned.m8n8.x2.trans.shared.b16 {%0,%1}, [%2];\n"
        : "=r"(r[0]), "=r"(r[1]) : "r"(addr));
}
__device__ __forceinline__ void cp_async16(uint32_t dst, const void* src, int src_bytes) {
    asm volatile("cp.async.cg.shared.global [%0], [%1], 16, %2;\n"
        :: "r"(dst), "l"(src), "r"(src_bytes));
}
__device__ __forceinline__ void cp_commit() {
    asm volatile("cp.async.commit_group;\n" ::: "memory");
}
template <int N>
__device__ __forceinline__ void cp_wait() {
    asm volatile("cp.async.wait_group %0;\n" :: "n"(N) : "memory");
}

// ---------------- pipelined tensor-core GEMM (fp16 in): G = A @ W ----------------
template <int DOUT>
__global__ __launch_bounds__(256) void gemm_tc_async(const __half* __restrict__ A,
                                                     const __half* __restrict__ W,
                                                     __half* __restrict__ G) {
    constexpr int BM = 128;
    constexpr int BK = 32;
    constexpr int NC = 128 / BK;
    constexpr int AP = BK + 8;
    constexpr int WP = DOUT + 8;
    constexpr int WN = 32;
    constexpr int WM = (DOUT == 128) ? 64 : 32;
    constexpr int MT = WM / 16;
    constexpr int NT = WN / 8;

    __shared__ __half As[2][BM * AP];
    __shared__ __half Ws[2][BK * WP];

    const int t = threadIdx.x;
    const int lane = t & 31;
    const int wid = t >> 5;
    const int warp_m = (DOUT == 128) ? (wid >> 2) : (wid >> 1);
    const int warp_n = (DOUT == 128) ? (wid & 3) : (wid & 1);
    const int row0 = blockIdx.x * BM;

    const uint32_t asb[2] = { (uint32_t)__cvta_generic_to_shared(&As[0][0]),
                              (uint32_t)__cvta_generic_to_shared(&As[1][0]) };
    const uint32_t wsb[2] = { (uint32_t)__cvta_generic_to_shared(&Ws[0][0]),
                              (uint32_t)__cvta_generic_to_shared(&Ws[1][0]) };

    auto issue_chunk = [&](int c, int st) {
        const int kc = c * BK;
#pragma unroll
        for (int s = t; s < BM * 4; s += 256) {
            int r = s >> 2, q = s & 3;
            int gr = row0 + r;
            const __half* src = A + (size_t)(gr < NN ? gr : 0) * 128 + kc + q * 8;
            cp_async16(asb[st] + (r * AP + q * 8) * 2, src, gr < NN ? 16 : 0);
        }
        constexpr int WQ = DOUT / 8;
#pragma unroll
        for (int s = t; s < BK * WQ; s += 256) {
            int r = s / WQ, q = s % WQ;
            cp_async16(wsb[st] + (r * WP + q * 8) * 2,
                       W + (size_t)(kc + r) * DOUT + q * 8, 16);
        }
        cp_commit();
    };

    float acc[MT][NT][4];
#pragma unroll
    for (int i = 0; i < MT; i++)
#pragma unroll
        for (int j = 0; j < NT; j++) {
            acc[i][j][0] = 0.f; acc[i][j][1] = 0.f;
            acc[i][j][2] = 0.f; acc[i][j][3] = 0.f;
        }

    issue_chunk(0, 0);

#pragma unroll
    for (int c = 0; c < NC; c++) {
        if (c + 1 < NC) {
            issue_chunk(c + 1, (c + 1) & 1);
            cp_wait<1>();
        } else {
            cp_wait<0>();
        }
        __syncthreads();

        const int st = c & 1;
#pragma unroll
        for (int k = 0; k < BK; k += 16) {
            unsigned afrag[MT][4];
            unsigned bfrag[NT][2];
#pragma unroll
            for (int mt = 0; mt < MT; mt++) {
                int row = warp_m * WM + mt * 16 + (lane & 15);
                int col = k + ((lane >> 4) << 3);
                ldsm_x4(afrag[mt], asb[st] + (row * AP + col) * 2);
            }
#pragma unroll
            for (int nt = 0; nt < NT; nt++) {
                int krow = k + (lane & 15);
                int col = warp_n * WN + nt * 8;
                ldsm_x2_trans(bfrag[nt], wsb[st] + (krow * WP + col) * 2);
            }
#pragma unroll
            for (int mt = 0; mt < MT; mt++)
#pragma unroll
                for (int nt = 0; nt < NT; nt++)
                    mma16816(acc[mt][nt], afrag[mt], bfrag[nt]);
        }
        __syncthreads();
    }

    const int gID = lane >> 2;
    const int tc = lane & 3;
#pragma unroll
    for (int mt = 0; mt < MT; mt++) {
#pragma unroll
        for (int nt = 0; nt < NT; nt++) {
            int col = warp_n * WN + nt * 8 + tc * 2;
            int r0 = row0 + warp_m * WM + mt * 16 + gID;
            if (r0 < NN) {
                __half2 p = __floats2half2_rn(acc[mt][nt][0], acc[mt][nt][1]);
                *(unsigned*)(G + (size_t)r0 * DOUT + col) = *(unsigned*)&p;
            }
            int r1 = r0 + 8;
            if (r1 < NN) {
                __half2 p = __floats2half2_rn(acc[mt][nt][2], acc[mt][nt][3]);
                *(unsigned*)(G + (size_t)r1 * DOUT + col) = *(unsigned*)&p;
            }
        }
    }
}

// ---------------- layer-1 GEMM (fp32 in, fused convert; non-pipelined, BK=64) ----------------
__global__ __launch_bounds__(256) void gemm_tc_f32(const float* __restrict__ A,
                                                   const __half* __restrict__ W,
                                                   __half* __restrict__ G) {
    constexpr int DOUT = 128;
    constexpr int BM = 128;
    constexpr int BK = 64;
    constexpr int AP = BK + 8;
    constexpr int WP = DOUT + 8;
    constexpr int WN = 32, WM = 64, MT = 4, NT = 4;

    __shared__ __half As[BM * AP];
    __shared__ __half Ws[BK * WP];

    const int t = threadIdx.x;
    const int lane = t & 31;
    const int wid = t >> 5;
    const int warp_m = wid >> 2;
    const int warp_n = wid & 3;
    const int row0 = blockIdx.x * BM;

    float acc[MT][NT][4];
#pragma unroll
    for (int i = 0; i < MT; i++)
#pragma unroll
        for (int j = 0; j < NT; j++) {
            acc[i][j][0] = 0.f; acc[i][j][1] = 0.f;
            acc[i][j][2] = 0.f; acc[i][j][3] = 0.f;
        }

    const uint32_t as_base = (uint32_t)__cvta_generic_to_shared(As);
    const uint32_t ws_base = (uint32_t)__cvta_generic_to_shared(Ws);

    for (int kc = 0; kc < 128; kc += BK) {
        constexpr int F4PR = BK / 4;
#pragma unroll
        for (int s = t; s < BM * F4PR; s += 256) {
            int r = s / F4PR, c4 = s % F4PR;
            float4 v = make_float4(0.f, 0.f, 0.f, 0.f);
            int gr = row0 + r;
            if (gr < NN) v = *((const float4*)(A + (size_t)gr * 128 + kc) + c4);
            __half2 p0 = __floats2half2_rn(v.x, v.y);
            __half2 p1 = __floats2half2_rn(v.z, v.w);
            uint2 o; o.x = *(unsigned*)&p0; o.y = *(unsigned*)&p1;
            *(uint2*)&As[r * AP + c4 * 4] = o;
        }
        constexpr int WU4 = DOUT / 8;
        uint4* dst = (uint4*)Ws;
#pragma unroll
        for (int s = t; s < BK * WU4; s += 256) {
            int r = s / WU4, c4 = s % WU4;
            dst[r * (WP / 8) + c4] = *((const uint4*)(W + (size_t)(kc + r) * DOUT) + c4);
        }
        __syncthreads();

#pragma unroll
        for (int k = 0; k < BK; k += 16) {
            unsigned afrag[MT][4];
            unsigned bfrag[NT][2];
#pragma unroll
            for (int mt = 0; mt < MT; mt++) {
                int row = warp_m * WM + mt * 16 + (lane & 15);
                int col = k + ((lane >> 4) << 3);
                ldsm_x4(afrag[mt], as_base + (row * AP + col) * 2);
            }
#pragma unroll
            for (int nt = 0; nt < NT; nt++) {
                int krow = k + (lane & 15);
                int col = warp_n * WN + nt * 8;
                ldsm_x2_trans(bfrag[nt], ws_base + (krow * WP + col) * 2);
            }
#pragma unroll
            for (int mt = 0; mt < MT; mt++)
#pragma unroll
                for (int nt = 0; nt < NT; nt++)
                    mma16816(acc[mt][nt], afrag[mt], bfrag[nt]);
        }
        __syncthreads();
    }

    const int gID = lane >> 2;
    const int tc = lane & 3;
#pragma unroll
    for (int mt = 0; mt < MT; mt++) {
#pragma unroll
        for (int nt = 0; nt < NT; nt++) {
            int col = warp_n * WN + nt * 8 + tc * 2;
            int r0 = row0 + warp_m * WM + mt * 16 + gID;
            if (r0 < NN) {
                __half2 p = __floats2half2_rn(acc[mt][nt][0], acc[mt][nt][1]);
                *(unsigned*)(G + (size_t)r0 * DOUT + col) = *(unsigned*)&p;
            }
            int r1 = r0 + 8;
            if (r1 < NN) {
                __half2 p = __floats2half2_rn(acc[mt][nt][2], acc[mt][nt][3]);
                *(unsigned*)(G + (size_t)r1 * DOUT + col) = *(unsigned*)&p;
            }
        }
    }
}

// ---------------- SpMM (CSR gather, fp16 in / fp16 out) ----------------
__global__ __launch_bounds__(256) void spmm128h_kernel(const __half* __restrict__ G,
                                                       const float* __restrict__ bias,
                                                       __half* __restrict__ out) {
    int r = (blockIdx.x * blockDim.x + threadIdx.x) >> 5;
    if (r >= NN) return;
    int lane = threadIdx.x & 31;
    int beg = g_rowptr[r], end = g_rowptr[r + 1];

    float4 acc = make_float4(0.f, 0.f, 0.f, 0.f);
    int e = beg;
#pragma unroll 1
    for (; e + 4 <= end; e += 4) {
        int2 e0 = g_edge[e];     int2 e1 = g_edge[e + 1];
        int2 e2 = g_edge[e + 2]; int2 e3 = g_edge[e + 3];
        uint2 qa = *((const uint2*)(G + (size_t)e0.x * 128) + lane);
        uint2 qb = *((const uint2*)(G + (size_t)e1.x * 128) + lane);
        uint2 qc = *((const uint2*)(G + (size_t)e2.x * 128) + lane);
        uint2 qd = *((const uint2*)(G + (size_t)e3.x * 128) + lane);
        float v0 = __int_as_float(e0.y), v1 = __int_as_float(e1.y);
        float v2 = __int_as_float(e2.y), v3 = __int_as_float(e3.y);
        float2 a0 = __half22float2(*(__half2*)&qa.x), a1 = __half22float2(*(__half2*)&qa.y);
        float2 b0 = __half22float2(*(__half2*)&qb.x), b1 = __half22float2(*(__half2*)&qb.y);
        float2 c0 = __half22float2(*(__half2*)&qc.x), c1 = __half22float2(*(__half2*)&qc.y);
        float2 d0 = __half22float2(*(__half2*)&qd.x), d1 = __half22float2(*(__half2*)&qd.y);
        acc.x += v0 * a0.x + v1 * b0.x + v2 * c0.x + v3 * d0.x;
        acc.y += v0 * a0.y + v1 * b0.y + v2 * c0.y + v3 * d0.y;
        acc.z += v0 * a1.x + v1 * b1.x + v2 * c1.x + v3 * d1.x;
        acc.w += v0 * a1.y + v1 * b1.y + v2 * c1.y + v3 * d1.y;
    }
#pragma unroll 1
    for (; e < end; e++) {
        int2 e0 = g_edge[e];
        float v0 = __int_as_float(e0.y);
        uint2 qa = *((const uint2*)(G + (size_t)e0.x * 128) + lane);
        float2 a0 = __half22float2(*(__half2*)&qa.x), a1 = __half22float2(*(__half2*)&qa.y);
        acc.x += v0 * a0.x; acc.y += v0 * a0.y;
        acc.z += v0 * a1.x; acc.w += v0 * a1.y;
    }
    float4 b4 = *((const float4*)bias + lane);
    acc.x = fmaxf(acc.x + b4.x, 0.f); acc.y = fmaxf(acc.y + b4.y, 0.f);
    acc.z = fmaxf(acc.z + b4.z, 0.f); acc.w = fmaxf(acc.w + b4.w, 0.f);
    __half2 p0 = __floats2half2_rn(acc.x, acc.y);
    __half2 p1 = __floats2half2_rn(acc.z, acc.w);
    uint2 o; o.x = *(unsigned*)&p0; o.y = *(unsigned*)&p1;
    *((uint2*)(out + (size_t)r * 128) + lane) = o;
}

__global__ __launch_bounds__(256) void spmm64_kernel(const __half* __restrict__ G,
                                                     const float* __restrict__ bias,
                                                     float* __restrict__ out) {
    int r = (blockIdx.x * blockDim.x + threadIdx.x) >> 5;
    if (r >= NN) return;
    int lane = threadIdx.x & 31;
    int beg = g_rowptr[r], end = g_rowptr[r + 1];

    float2 acc = make_float2(0.f, 0.f);
    int e = beg;
#pragma unroll 1
    for (; e + 4 <= end; e += 4) {
        int2 e0 = g_edge[e];     int2 e1 = g_edge[e + 1];
        int2 e2 = g_edge[e + 2]; int2 e3 = g_edge[e + 3];
        unsigned qa = *((const unsigned*)(G + (size_t)e0.x * 64) + lane);
        unsigned qb = *((const unsigned*)(G + (size_t)e1.x * 64) + lane);
        unsigned qc = *((const unsigned*)(G + (size_t)e2.x * 64) + lane);
        unsigned qd = *((const unsigned*)(G + (size_t)e3.x * 64) + lane);
        float v0 = __int_as_float(e0.y), v1 = __int_as_float(e1.y);
        float v2 = __int_as_float(e2.y), v3 = __int_as_float(e3.y);
        float2 a = __half22float2(*(__half2*)&qa);
        float2 b = __half22float2(*(__half2*)&qb);
        float2 c = __half22float2(*(__half2*)&qc);
        float2 d = __half22float2(*(__half2*)&qd);
        acc.x += v0 * a.x + v1 * b.x + v2 * c.x + v3 * d.x;
        acc.y += v0 * a.y + v1 * b.y + v2 * c.y + v3 * d.y;
    }
#pragma unroll 1
    for (; e < end; e++) {
        int2 e0 = g_edge[e];
        float v0 = __int_as_float(e0.y);
        unsigned qa = *((const unsigned*)(G + (size_t)e0.x * 64) + lane);
        float2 a = __half22float2(*(__half2*)&qa);
        acc.x += v0 * a.x; acc.y += v0 * a.y;
    }
    float2 b2 = *((const float2*)bias + lane);
    acc.x += b2.x; acc.y += b2.y;
    *((float2*)(out + (size_t)r * 64) + lane) = acc;
}

// ---------------- launch ----------------
extern "C" void kernel_launch(void* const* d_in, const int* in_sizes, int n_in,
                              void* d_out, int out_size) {
    (void)n_in; (void)out_size;
    const float* X    = (const float*)d_in[0];
    const int*   rows = (const int*)  d_in[1];
    const int*   cols = (const int*)  d_in[2];
    const float* vals = (const float*)d_in[3];
    const float* W1   = (const float*)d_in[4];
    const float* b1   = (const float*)d_in[5];
    const float* W2   = (const float*)d_in[6];
    const float* b2   = (const float*)d_in[7];
    const float* W3   = (const float*)d_in[8];
    const float* b3   = (const float*)d_in[9];
    float* out = (float*)d_out;
    const int nnz = in_sizes[1];

    __half *A = nullptr, *G = nullptr, *W1h = nullptr, *W2h = nullptr, *W3h = nullptr;
    cudaGetSymbolAddress((void**)&A, g_A);
    cudaGetSymbolAddress((void**)&G, g_G);
    cudaGetSymbolAddress((void**)&W1h, g_W1h);
    cudaGetSymbolAddress((void**)&W2h, g_W2h);
    cudaGetSymbolAddress((void**)&W3h, g_W3h);

    const int TB = 256;
    const int spmm_blocks = (NN + 7) / 8;
    const int gemm_blocks = (NN + 127) / 128;
    const int e4_blocks = (nnz + TB * 4 - 1) / (TB * 4);

    // prep on main stream (deg zero for CSR, weights for GEMMs)
    prep_kernel<<<NB_Z + 32 + 8, TB>>>(W1, W2, W3);

    // fork: CSR chain on side stream, concurrent with layer-1 GEMM on main stream
    cudaEventRecord(g_ev_fork, 0);
    cudaStreamWaitEvent(g_side, g_ev_fork, 0);

    histo_kernel<<<e4_blocks, TB, 0, g_side>>>(rows, nnz);
    scan1_kernel<<<NB2, 512, 0, g_side>>>();
    scan3_kernel<<<NB2, 512, 0, g_side>>>();
    scatter_kernel<<<e4_blocks, TB, 0, g_side>>>(rows, cols, vals, nnz);
    cudaEventRecord(g_ev_join, g_side);

    // main stream: layer-1 GEMM (independent of CSR)
    gemm_tc_f32<<<gemm_blocks, TB>>>(X, W1h, G);

    // join: spmm needs both CSR and G
    cudaStreamWaitEvent(0, g_ev_join, 0);

    spmm128h_kernel<<<spmm_blocks, TB>>>(G, b1, A);

    gemm_tc_async<128><<<gemm_blocks, TB>>>(A, W2h, G);
    spmm128h_kernel<<<spmm_blocks, TB>>>(G, b2, A);

    gemm_tc_async<64><<<gemm_blocks, TB>>>(A, W3h, G);
    spmm64_kernel<<<spmm_blocks, TB>>>(G, b3, out);
}